// round 12
// baseline (speedup 1.0000x reference)
#include <cuda_runtime.h>
#include <cuda_bf16.h>
#include <math.h>

#define BATCH  1024
#define SEQN   128
#define DMODEL 256
#define NROWS  (BATCH*SEQN)            // 131072
#define ELEMS  (BATCH*SEQN*DMODEL)     // 33554432
#define SST    132

// bf16 GEMM smem layout, u32 units. Row stride = 20 u32 (32 bf16 + pad) = 80 B.
#define RSTR 20
#define UA_H 0
#define UA_L (128*RSTR)
#define UB_H (2*128*RSTR)
#define UB_L (3*128*RSTR)
#define SM_GEMM_U32 (4*128*RSTR)     // 10240 u32 = 40960 B

// sa_attn smem layout (u32 units). Row stride 68 u32.
#define QSTR 68
#define OQH 0
#define OQL (128*QSTR)
#define OKH (2*128*QSTR)
#define OKL (3*128*QSTR)
#define OPT (4*128*QSTR)
#define SM_ATTN_U32 (4*128*QSTR + 128*SST)   // 206848 B

// packed weight offsets (u32)
#define WO_SAQ  0
#define WO_SAK  32768
#define WO_SAV  65536
#define WO_SAF  98304
#define WO_MS1  131072   // 256 n x 192 kp
#define WO_MS2  180224
#define WO_CAQ  212992
#define WO_CAK  245760
#define WO_CAV  278528
#define W_TOTAL 311296

// ---------------- scratch ----------------
__device__ float g_KV[ELEMS];
__device__ float g_Q [ELEMS];
__device__ float g_K [ELEMS];
__device__ float g_V [ELEMS];
__device__ float g_AO[ELEMS];
__device__ float g_FC[ELEMS];
__device__ float g_SA[ELEMS];
__device__ float g_H1[ELEMS];
__device__ float g_KC[ELEMS];
__device__ float g_KH[ELEMS];
__device__ float g_VH[ELEMS];
__device__ float g_QH[BATCH*DMODEL];
__device__ unsigned g_WH[W_TOTAL];
__device__ unsigned g_WL[W_TOTAL];
__device__ unsigned char g_mask8[NROWS];
__device__ int g_mask_mode;

// ---------------- bf16 helpers ----------------
__device__ __forceinline__ unsigned pack_bf16x2(float lo, float hi) {
    unsigned r;
    asm("cvt.rn.bf16x2.f32 %0, %1, %2;" : "=r"(r) : "f"(hi), "f"(lo));
    return r;
}
__device__ __forceinline__ float lo_bf16f(unsigned u) { return __uint_as_float(u << 16); }
__device__ __forceinline__ float hi_bf16f(unsigned u) { return __uint_as_float(u & 0xFFFF0000u); }
__device__ __forceinline__ void split_pair(float f0, float f1, unsigned& h, unsigned& l) {
    h = pack_bf16x2(f0, f1);
    l = pack_bf16x2(f0 - lo_bf16f(h), f1 - hi_bf16f(h));
}
__device__ __forceinline__ void mma_bf16(float* d, const unsigned* a, const unsigned* b) {
    asm volatile(
        "mma.sync.aligned.m16n8k16.row.col.f32.bf16.bf16.f32 "
        "{%0,%1,%2,%3}, {%4,%5,%6,%7}, {%8,%9}, {%0,%1,%2,%3};\n"
        : "+f"(d[0]), "+f"(d[1]), "+f"(d[2]), "+f"(d[3])
        : "r"(a[0]), "r"(a[1]), "r"(a[2]), "r"(a[3]),
          "r"(b[0]), "r"(b[1]));
}

// ---------------- mask dtype detection + normalization ----------------
__global__ void detect_mask_kernel(const void* mask) {
    if (threadIdx.x == 0 && blockIdx.x == 0) {
        const unsigned* p = (const unsigned*)mask;
        int mode = 1;
        for (int i = 0; i < 1024; i++) {
            unsigned v = p[i];
            if (v == 0x3F800000u) { mode = 2; break; }
            if (v > 1u) { mode = 0; break; }
        }
        g_mask_mode = mode;
    }
}

__global__ __launch_bounds__(256) void norm_mask_kernel(const void* mask) {
    int i = blockIdx.x * 256 + threadIdx.x;
    if (i >= NROWS) return;
    int mode = g_mask_mode;
    unsigned char m;
    if (mode == 0)      m = (((const unsigned char*)mask)[i] != 0);
    else if (mode == 1) m = (((const int*)mask)[i] != 0);
    else                m = (((const float*)mask)[i] != 0.f);
    g_mask8[i] = m;
}

// ---------------- concat([seq, seq_t], -1) -> KV ----------------
__global__ __launch_bounds__(256) void concat_kv_kernel(
    const float* __restrict__ seq, const float* __restrict__ seqt)
{
    long i4 = (long)blockIdx.x * 256 + threadIdx.x;
    if (i4 >= (long)ELEMS / 4) return;
    long row = i4 >> 6;
    int  c4  = (int)(i4 & 63);
    float4 v;
    if (c4 < 32) v = ((const float4*)(seq  + row * 128))[c4];
    else         v = ((const float4*)(seqt + row * 128))[c4 - 32];
    ((float4*)(g_KV + row * 256))[c4] = v;
}

// ---------------- weight pack: W[Kt,N] -> [n][kp] hi/lo (R9-proven layout) ----------------
__global__ __launch_bounds__(256) void pack_w_kernel(
    const float* __restrict__ W, int Kt, int N,
    unsigned* __restrict__ oh, unsigned* __restrict__ ol)
{
    int idx = blockIdx.x * 256 + threadIdx.x;
    int khalf = Kt >> 1;
    if (idx >= N * khalf) return;
    int n = idx / khalf, kp = idx - n * khalf;
    float f0 = W[(2 * kp) * N + n];
    float f1 = W[(2 * kp + 1) * N + n];
    unsigned h, l;
    split_pair(f0, f1, h, l);
    oh[idx] = h;
    ol[idx] = l;
}

// ---------------- 3xBF16 tensor-core GEMM; A split in-kernel, W pre-packed ----------------
// C[M,N] = concat(A1,A2)[M,Ktot] @ W[Ktot,Ncols] (+bias)(+res)(relu)
// BM=128, BN=128, BK=32; 256 thr; warps 4(m)x2(n); warp tile 32x64.
__global__ __launch_bounds__(256, 2) void gemm_tc_kernel(
    const float* __restrict__ A1, int K1, int lda1,
    const float* __restrict__ A2, int lda2,
    const unsigned* __restrict__ Wh, const unsigned* __restrict__ Wl, int Ktot, int Ncols,
    const float* __restrict__ bias,
    const float* __restrict__ res,
    int relu,
    float* __restrict__ C)
{
    extern __shared__ unsigned su[];
    unsigned* sAh = su + UA_H;
    unsigned* sAl = su + UA_L;
    unsigned* sBh = su + UB_H;
    unsigned* sBl = su + UB_L;

    const int tid  = threadIdx.x;
    const int warp = tid >> 5, lane = tid & 31;
    const int wm = warp & 3, wn = warp >> 2;
    const int group = lane >> 2, tig = lane & 3;
    const long m0 = (long)blockIdx.y * 128;
    const int  n0 = blockIdx.x * 128;
    const int wmb = wm * 32;
    const int wnb = wn * 64;
    const int khalf = Ktot >> 1;

    float acc[2][8][4];
#pragma unroll
    for (int mi = 0; mi < 2; mi++)
#pragma unroll
        for (int ni = 0; ni < 8; ni++)
#pragma unroll
            for (int q = 0; q < 4; q++) acc[mi][ni][q] = 0.f;

    const int nk = Ktot / 32;

    for (int ck = 0; ck < nk; ck++) {
        const int k0 = ck * 32;
        const int k0p = ck * 16;
        if (ck > 0) __syncthreads();

        // ---- stage A: load fp32, split, store [m][kp] ----
#pragma unroll
        for (int i = 0; i < 4; i++) {
            int f4 = tid + i * 256;
            int row = f4 >> 3, c = (f4 & 7) * 4;
            const float* ap = (k0 < K1) ? (A1 + (m0 + row) * (long)lda1 + k0 + c)
                                        : (A2 + (m0 + row) * (long)lda2 + (k0 - K1) + c);
            float4 v = *(const float4*)ap;
            unsigned h0, l0, h1, l1;
            split_pair(v.x, v.y, h0, l0);
            split_pair(v.z, v.w, h1, l1);
            int ui = row * RSTR + (c >> 1);
            *(uint2*)&sAh[ui] = make_uint2(h0, h1);
            *(uint2*)&sAl[ui] = make_uint2(l0, l1);
        }
        // ---- stage B: pure copy from pre-packed weights [n][kp] ----
#pragma unroll
        for (int i = 0; i < 4; i++) {
            int task = tid + i * 256;
            int kq = task & 7;             // 2 u32 each
            int n  = task >> 3;
            long wi = (long)(n0 + n) * khalf + k0p + kq * 2;
            uint2 h = *(const uint2*)&Wh[wi];
            uint2 l = *(const uint2*)&Wl[wi];
            int ui = n * RSTR + kq * 2;
            *(uint2*)&sBh[ui] = h;
            *(uint2*)&sBl[ui] = l;
        }
        __syncthreads();

        // ---- compute: proven R8 loop ----
#pragma unroll
        for (int ks = 0; ks < 2; ks++) {
            const int kb8 = ks * 8;
            unsigned ah[2][4], al[2][4];
#pragma unroll
            for (int mi = 0; mi < 2; mi++) {
                int r = wmb + mi * 16 + group;
                int i0 = r * RSTR + kb8 + tig;
                int i1 = (r + 8) * RSTR + kb8 + tig;
                ah[mi][0] = sAh[i0];
                ah[mi][1] = sAh[i1];
                ah[mi][2] = sAh[i0 + 4];
                ah[mi][3] = sAh[i1 + 4];
                al[mi][0] = sAl[i0];
                al[mi][1] = sAl[i1];
                al[mi][2] = sAl[i0 + 4];
                al[mi][3] = sAl[i1 + 4];
            }
#pragma unroll
            for (int nt = 0; nt < 8; nt++) {
                int nrow = wnb + nt * 8 + group;
                int bi = nrow * RSTR + kb8 + tig;
                unsigned bh[2], bl[2];
                bh[0] = sBh[bi];
                bh[1] = sBh[bi + 4];
                bl[0] = sBl[bi];
                bl[1] = sBl[bi + 4];
#pragma unroll
                for (int mi = 0; mi < 2; mi++) {
                    mma_bf16(acc[mi][nt], ah[mi], bh);
                    mma_bf16(acc[mi][nt], al[mi], bh);
                    mma_bf16(acc[mi][nt], ah[mi], bl);
                }
            }
        }
    }

#pragma unroll
    for (int mi = 0; mi < 2; mi++) {
        long gm = m0 + wmb + mi * 16 + group;
#pragma unroll
        for (int ni = 0; ni < 8; ni++) {
            int gc = n0 + wnb + ni * 8 + 2 * tig;
            float v0 = acc[mi][ni][0], v1 = acc[mi][ni][1];
            float v2 = acc[mi][ni][2], v3 = acc[mi][ni][3];
            if (bias) {
                float b0 = bias[gc], b1 = bias[gc + 1];
                v0 += b0; v1 += b1; v2 += b0; v3 += b1;
            }
            if (res) {
                float2 r0 = *(const float2*)(res + gm * Ncols + gc);
                float2 r1 = *(const float2*)(res + (gm + 8) * Ncols + gc);
                v0 += r0.x; v1 += r0.y; v2 += r1.x; v3 += r1.y;
            }
            if (relu) {
                v0 = fmaxf(v0, 0.f); v1 = fmaxf(v1, 0.f);
                v2 = fmaxf(v2, 0.f); v3 = fmaxf(v3, 0.f);
            }
            *(float2*)(C + gm * Ncols + gc)       = make_float2(v0, v1);
            *(float2*)(C + (gm + 8) * Ncols + gc) = make_float2(v2, v3);
        }
    }
}

// ---------------- self-attention: full bf16 tensor-core (R10 proven) ----------------
__global__ __launch_bounds__(256) void sa_attn_kernel(
    const float* __restrict__ Q, const float* __restrict__ K, const float* __restrict__ V,
    const unsigned char* __restrict__ mask, float* __restrict__ O)
{
    extern __shared__ unsigned su[];
    float* sPt = (float*)(su + OPT);
    __shared__ unsigned char smask[128];

    const int h = blockIdx.x, b = blockIdx.y;
    const int tid = threadIdx.x;
    const int warp = tid >> 5, lane = tid & 31;
    const int group = lane >> 2, tig = lane & 3;
    const float* Qp = Q + ((long)b * SEQN) * DMODEL + h * 128;
    const float* Kp = K + ((long)b * SEQN) * DMODEL + h * 128;
    const float* Vp = V + ((long)b * SEQN) * DMODEL + h * 128;
    const float invs = 0.0883883476483184f;

    const int wm = warp & 3;
    const int wmb = wm * 32, wnb = (warp >> 2) * 64;

    if (tid < 128) smask[tid] = mask[(long)b * SEQN + tid];
    for (int idx = tid; idx < 128 * 32; idx += 256) {
        int r = idx >> 5;
        int c = (idx & 31) << 2;
        int ui = r * QSTR + (c >> 1);
        float4 qv = *(const float4*)(Qp + (long)r * DMODEL + c);
        qv.x *= invs; qv.y *= invs; qv.z *= invs; qv.w *= invs;
        unsigned h0, l0, h1, l1;
        split_pair(qv.x, qv.y, h0, l0);
        split_pair(qv.z, qv.w, h1, l1);
        *(uint2*)&su[OQH + ui] = make_uint2(h0, h1);
        *(uint2*)&su[OQL + ui] = make_uint2(l0, l1);
        float4 kv = *(const float4*)(Kp + (long)r * DMODEL + c);
        split_pair(kv.x, kv.y, h0, l0);
        split_pair(kv.z, kv.w, h1, l1);
        *(uint2*)&su[OKH + ui] = make_uint2(h0, h1);
        *(uint2*)&su[OKL + ui] = make_uint2(l0, l1);
    }
    __syncthreads();

    {
        float acc[2][8][4];
#pragma unroll
        for (int mi = 0; mi < 2; mi++)
#pragma unroll
            for (int ni = 0; ni < 8; ni++)
#pragma unroll
                for (int q = 0; q < 4; q++) acc[mi][ni][q] = 0.f;

#pragma unroll
        for (int ks = 0; ks < 8; ks++) {
            const int kb8 = ks * 8;
            unsigned ah[2][4], al[2][4];
#pragma unroll
            for (int mi = 0; mi < 2; mi++) {
                int r = wmb + mi * 16 + group;
                int i0 = r * QSTR + kb8 + tig;
                int i1 = (r + 8) * QSTR + kb8 + tig;
                ah[mi][0] = su[OQH + i0];
                ah[mi][1] = su[OQH + i1];
                ah[mi][2] = su[OQH + i0 + 4];
                ah[mi][3] = su[OQH + i1 + 4];
                al[mi][0] = su[OQL + i0];
                al[mi][1] = su[OQL + i1];
                al[mi][2] = su[OQL + i0 + 4];
                al[mi][3] = su[OQL + i1 + 4];
            }
#pragma unroll
            for (int nt = 0; nt < 8; nt++) {
                int nrow = wnb + nt * 8 + group;
                int bi = nrow * QSTR + kb8 + tig;
                unsigned bh[2], bl[2];
                bh[0] = su[OKH + bi];
                bh[1] = su[OKH + bi + 4];
                bl[0] = su[OKL + bi];
                bl[1] = su[OKL + bi + 4];
#pragma unroll
                for (int mi = 0; mi < 2; mi++) {
                    mma_bf16(acc[mi][nt], ah[mi], bh);
                    mma_bf16(acc[mi][nt], al[mi], bh);
                    mma_bf16(acc[mi][nt], ah[mi], bl);
                }
            }
        }
#pragma unroll
        for (int mi = 0; mi < 2; mi++) {
            int gm0 = wmb + mi * 16 + group;
#pragma unroll
            for (int ni = 0; ni < 8; ni++) {
                int gc0 = wnb + ni * 8 + 2 * tig;
                sPt[gc0 * SST + gm0]           = acc[mi][ni][0];
                sPt[(gc0 + 1) * SST + gm0]     = acc[mi][ni][1];
                sPt[gc0 * SST + gm0 + 8]       = acc[mi][ni][2];
                sPt[(gc0 + 1) * SST + gm0 + 8] = acc[mi][ni][3];
            }
        }
    }
    __syncthreads();

    for (int r = warp; r < 128; r += 8) {
        float vv[4];
        float mx = -1e30f;
#pragma unroll
        for (int q = 0; q < 4; q++) {
            int c = lane + q * 32;
            float s = sPt[c * SST + r];
            if (smask[c]) s = -1e10f;
            vv[q] = s; mx = fmaxf(mx, s);
        }
#pragma unroll
        for (int o = 16; o > 0; o >>= 1) mx = fmaxf(mx, __shfl_xor_sync(0xffffffffu, mx, o));
        float sum = 0.f;
#pragma unroll
        for (int q = 0; q < 4; q++) { vv[q] = expf(vv[q] - mx); sum += vv[q]; }
#pragma unroll
        for (int o = 16; o > 0; o >>= 1) sum += __shfl_xor_sync(0xffffffffu, sum, o);
        float rs = 1.f / sum;
#pragma unroll
        for (int q = 0; q < 4; q++) sPt[(lane + q * 32) * SST + r] = vv[q] * rs;
    }
    __syncthreads();

    for (int idx = tid; idx < 128 * 64; idx += 256) {
        int q = idx >> 6, kp = idx & 63;
        float p0 = sPt[(2 * kp) * SST + q];
        float p1 = sPt[(2 * kp + 1) * SST + q];
        unsigned hh, ll;
        split_pair(p0, p1, hh, ll);
        su[OQH + q * QSTR + kp] = hh;
        su[OQL + q * QSTR + kp] = ll;
    }
    for (int idx = tid; idx < 64 * 32; idx += 256) {
        int kplow = idx & 15;
        int rest  = idx >> 4;
        int c4 = rest & 31;
        int kp = (rest >> 5) * 16 + kplow;
        int c = c4 * 4;
        float4 v0 = *(const float4*)(Vp + (long)(2 * kp) * DMODEL + c);
        float4 v1 = *(const float4*)(Vp + (long)(2 * kp + 1) * DMODEL + c);
        unsigned hh, ll;
        split_pair(v0.x, v1.x, hh, ll);
        su[OKH + (c + 0) * QSTR + kp] = hh; su[OKL + (c + 0) * QSTR + kp] = ll;
        split_pair(v0.y, v1.y, hh, ll);
        su[OKH + (c + 1) * QSTR + kp] = hh; su[OKL + (c + 1) * QSTR + kp] = ll;
        split_pair(v0.z, v1.z, hh, ll);
        su[OKH + (c + 2) * QSTR + kp] = hh; su[OKL + (c + 2) * QSTR + kp] = ll;
        split_pair(v0.w, v1.w, hh, ll);
        su[OKH + (c + 3) * QSTR + kp] = hh; su[OKL + (c + 3) * QSTR + kp] = ll;
    }
    __syncthreads();

    {
        float acc[2][8][4];
#pragma unroll
        for (int mi = 0; mi < 2; mi++)
#pragma unroll
            for (int ni = 0; ni < 8; ni++)
#pragma unroll
                for (int q = 0; q < 4; q++) acc[mi][ni][q] = 0.f;

#pragma unroll
        for (int ks = 0; ks < 8; ks++) {
            const int kb8 = ks * 8;
            unsigned ah[2][4], al[2][4];
#pragma unroll
            for (int mi = 0; mi < 2; mi++) {
                int r = wmb + mi * 16 + group;
                int i0 = r * QSTR + kb8 + tig;
                int i1 = (r + 8) * QSTR + kb8 + tig;
                ah[mi][0] = su[OQH + i0];
                ah[mi][1] = su[OQH + i1];
                ah[mi][2] = su[OQH + i0 + 4];
                ah[mi][3] = su[OQH + i1 + 4];
                al[mi][0] = su[OQL + i0];
                al[mi][1] = su[OQL + i1];
                al[mi][2] = su[OQL + i0 + 4];
                al[mi][3] = su[OQL + i1 + 4];
            }
#pragma unroll
            for (int nt = 0; nt < 8; nt++) {
                int nrow = wnb + nt * 8 + group;
                int bi = nrow * QSTR + kb8 + tig;
                unsigned bh[2], bl[2];
                bh[0] = su[OKH + bi];
                bh[1] = su[OKH + bi + 4];
                bl[0] = su[OKL + bi];
                bl[1] = su[OKL + bi + 4];
#pragma unroll
                for (int mi = 0; mi < 2; mi++) {
                    mma_bf16(acc[mi][nt], ah[mi], bh);
                    mma_bf16(acc[mi][nt], al[mi], bh);
                    mma_bf16(acc[mi][nt], ah[mi], bl);
                }
            }
        }

        float* Op = O + ((long)b * SEQN) * DMODEL + h * 128;
#pragma unroll
        for (int mi = 0; mi < 2; mi++) {
            int gm = wmb + mi * 16 + group;
#pragma unroll
            for (int nt = 0; nt < 8; nt++) {
                int gc = wnb + nt * 8 + 2 * tig;
                *(float2*)(Op + (long)gm * DMODEL + gc)       = make_float2(acc[mi][nt][0], acc[mi][nt][1]);
                *(float2*)(Op + (long)(gm + 8) * DMODEL + gc) = make_float2(acc[mi][nt][2], acc[mi][nt][3]);
            }
        }
    }
}

// ---------------- LayerNorm over 256, warp per row ----------------
__global__ __launch_bounds__(256) void ln_kernel(
    const float* __restrict__ X, const float* __restrict__ gw,
    const float* __restrict__ bw, float* __restrict__ Y)
{
    long row = (long)blockIdx.x * 8 + (threadIdx.x >> 5);
    int lane = threadIdx.x & 31;
    const float* xp = X + row * 256 + lane * 8;
    float4 a = *(const float4*)xp;
    float4 b = *(const float4*)(xp + 4);
    float s = a.x + a.y + a.z + a.w + b.x + b.y + b.z + b.w;
#pragma unroll
    for (int o = 16; o > 0; o >>= 1) s += __shfl_xor_sync(0xffffffffu, s, o);
    float mean = s * 0.00390625f;
    float q = 0.f;
    q += (a.x - mean) * (a.x - mean); q += (a.y - mean) * (a.y - mean);
    q += (a.z - mean) * (a.z - mean); q += (a.w - mean) * (a.w - mean);
    q += (b.x - mean) * (b.x - mean); q += (b.y - mean) * (b.y - mean);
    q += (b.z - mean) * (b.z - mean); q += (b.w - mean) * (b.w - mean);
#pragma unroll
    for (int o = 16; o > 0; o >>= 1) q += __shfl_xor_sync(0xffffffffu, q, o);
    float rstd = rsqrtf(q * 0.00390625f + 1e-5f);
    int c = lane * 8;
    float4 g0 = *(const float4*)(gw + c), g1 = *(const float4*)(gw + c + 4);
    float4 b0 = *(const float4*)(bw + c), b1 = *(const float4*)(bw + c + 4);
    float4 o0, o1;
    o0.x = (a.x - mean) * rstd * g0.x + b0.x;
    o0.y = (a.y - mean) * rstd * g0.y + b0.y;
    o0.z = (a.z - mean) * rstd * g0.z + b0.z;
    o0.w = (a.w - mean) * rstd * g0.w + b0.w;
    o1.x = (b.x - mean) * rstd * g1.x + b1.x;
    o1.y = (b.y - mean) * rstd * g1.y + b1.y;
    o1.z = (b.z - mean) * rstd * g1.z + b1.z;
    o1.w = (b.w - mean) * rstd * g1.w + b1.w;
    *(float4*)(Y + row * 256 + c)     = o0;
    *(float4*)(Y + row * 256 + c + 4) = o1;
}

// ---------------- cross-attention + fc + LN + output MLP ----------------
__global__ __launch_bounds__(256) void ca_kernel(
    const float* __restrict__ QH, const float* __restrict__ KH, const float* __restrict__ VH,
    const unsigned char* __restrict__ mask,
    const float* __restrict__ fcw, const float* __restrict__ fcb,
    const float* __restrict__ lng, const float* __restrict__ lnb,
    const float* __restrict__ src, const float* __restrict__ srct,
    const float* __restrict__ w1, const float* __restrict__ b1,
    const float* __restrict__ w2, const float* __restrict__ b2,
    float* __restrict__ out_vec, float* __restrict__ out_attn)
{
    const int b = blockIdx.x;
    const int tid = threadIdx.x;
    __shared__ float s_q[256], s_p[256], s_o[256], s_y[256], s_h[128], s_red[16];

    s_q[tid] = QH[(long)b * 256 + tid];
    __syncthreads();

    const int h = tid >> 7, k = tid & 127;
    const int lane = tid & 31, warp = tid >> 5;

    const float* krow = KH + ((long)b * 128 + k) * 256 + h * 128;
    float s = 0.f;
#pragma unroll 8
    for (int d = 0; d < 128; d += 4) {
        float4 kv = *(const float4*)(krow + d);
        s += s_q[h * 128 + d + 0] * kv.x + s_q[h * 128 + d + 1] * kv.y
           + s_q[h * 128 + d + 2] * kv.z + s_q[h * 128 + d + 3] * kv.w;
    }
    s *= 0.0883883476483184f;
    if (mask[(long)b * 128 + k]) s = -1e10f;

    float mx = s;
#pragma unroll
    for (int o = 16; o > 0; o >>= 1) mx = fmaxf(mx, __shfl_xor_sync(0xffffffffu, mx, o));
    if (lane == 0) s_red[warp] = mx;
    __syncthreads();
    mx = fmaxf(fmaxf(s_red[h * 4 + 0], s_red[h * 4 + 1]),
               fmaxf(s_red[h * 4 + 2], s_red[h * 4 + 3]));
    float e = expf(s - mx);
    float sum = e;
#pragma unroll
    for (int o = 16; o > 0; o >>= 1) sum += __shfl_xor_sync(0xffffffffu, sum, o);
    if (lane == 0) s_red[8 + warp] = sum;
    __syncthreads();
    sum = s_red[8 + h * 4 + 0] + s_red[8 + h * 4 + 1] + s_red[8 + h * 4 + 2] + s_red[8 + h * 4 + 3];
    float p = e / sum;
    s_p[tid] = p;
    out_attn[((long)h * BATCH + b) * 128 + k] = p;
    __syncthreads();

    const int d = tid & 127;
    float o = 0.f;
#pragma unroll 8
    for (int kk = 0; kk < 128; kk++)
        o += s_p[h * 128 + kk] * VH[((long)b * 128 + kk) * 256 + h * 128 + d];
    s_o[tid] = o;
    __syncthreads();

    float y = fcb[tid];
    for (int i = 0; i < 256; i++) y += s_o[i] * fcw[i * 256 + tid];
    y += (tid < 128) ? src[(long)b * 128 + tid] : srct[(long)b * 128 + tid - 128];

    float t = y;
#pragma unroll
    for (int ofs = 16; ofs > 0; ofs >>= 1) t += __shfl_xor_sync(0xffffffffu, t, ofs);
    if (lane == 0) s_red[warp] = t;
    __syncthreads();
    float mean = (s_red[0] + s_red[1] + s_red[2] + s_red[3] +
                  s_red[4] + s_red[5] + s_red[6] + s_red[7]) * 0.00390625f;
    float dv = y - mean;
    t = dv * dv;
#pragma unroll
    for (int ofs = 16; ofs > 0; ofs >>= 1) t += __shfl_xor_sync(0xffffffffu, t, ofs);
    if (lane == 0) s_red[8 + warp] = t;
    __syncthreads();
    float var = (s_red[8] + s_red[9] + s_red[10] + s_red[11] +
                 s_red[12] + s_red[13] + s_red[14] + s_red[15]) * 0.00390625f;
    float rstd = rsqrtf(var + 1e-5f);
    s_y[tid] = dv * rstd * lng[tid] + lnb[tid];
    __syncthreads();

    if (tid < 128) {
        float hh = b1[tid];
        for (int i = 0; i < 256; i++) hh += s_y[i] * w1[i * 128 + tid];
        for (int i = 0; i < 128; i++) hh += src[(long)b * 128 + i] * w1[(256 + i) * 128 + tid];
        s_h[tid] = fmaxf(hh, 0.f);
    }
    __syncthreads();
    if (tid < 128) {
        float oo = b2[tid];
        for (int i = 0; i < 128; i++) oo += s_h[i] * w2[i * 128 + tid];
        out_vec[(long)b * 128 + tid] = oo;
    }
}

// ---------------- host ----------------
static void* sym_addr(const void* s) {
    void* p = nullptr;
    cudaGetSymbolAddress(&p, s);
    return p;
}

extern "C" void kernel_launch(void* const* d_in, const int* in_sizes, int n_in,
                              void* d_out, int out_size)
{
    const float* src   = (const float*)d_in[0];
    const float* srct  = (const float*)d_in[1];
    const float* seq   = (const float*)d_in[2];
    const float* seqt  = (const float*)d_in[3];
    const void*  maskraw = d_in[4];

    const float *sa_wq, *sa_wk, *sa_wv, *sa_fcw, *sa_fcb, *sa_lng, *sa_lnb;
    const float *ms_w1, *ms_b1, *ms_w2, *ms_b2;
    const float *ca_wq, *ca_wk, *ca_wv, *ca_fcw, *ca_fcb, *ca_lng, *ca_lnb;
    const float *mg_w1, *mg_b1, *mg_w2, *mg_b2;

    bool dict_order = (in_sizes[10] == 98304);
    if (dict_order) {
        sa_wq  = (const float*)d_in[5];
        sa_wk  = (const float*)d_in[6];
        sa_wv  = (const float*)d_in[7];
        sa_fcw = (const float*)d_in[8];
        sa_fcb = (const float*)d_in[9];
        ms_w1  = (const float*)d_in[10];
        ms_b1  = (const float*)d_in[11];
        ms_w2  = (const float*)d_in[12];
        ms_b2  = (const float*)d_in[13];
        ca_wq  = (const float*)d_in[14];
        ca_wk  = (const float*)d_in[15];
        ca_wv  = (const float*)d_in[16];
        ca_fcw = (const float*)d_in[17];
        ca_fcb = (const float*)d_in[18];
        mg_w1  = (const float*)d_in[19];
        mg_b1  = (const float*)d_in[20];
        mg_w2  = (const float*)d_in[21];
        mg_b2  = (const float*)d_in[22];
        sa_lng = (const float*)d_in[23];
        sa_lnb = (const float*)d_in[24];
        ca_lng = (const float*)d_in[25];
        ca_lnb = (const float*)d_in[26];
    } else {
        sa_wq  = (const float*)d_in[5];
        sa_wk  = (const float*)d_in[6];
        sa_wv  = (const float*)d_in[7];
        sa_fcw = (const float*)d_in[8];
        sa_fcb = (const float*)d_in[9];
        sa_lng = (const float*)d_in[10];
        sa_lnb = (const float*)d_in[11];
        ms_w1  = (const float*)d_in[12];
        ms_b1  = (const float*)d_in[13];
        ms_w2  = (const float*)d_in[14];
        ms_b2  = (const float*)d_in[15];
        ca_wq  = (const float*)d_in[16];
        ca_wk  = (const float*)d_in[17];
        ca_wv  = (const float*)d_in[18];
        ca_fcw = (const float*)d_in[19];
        ca_fcb = (const float*)d_in[20];
        ca_lng = (const float*)d_in[21];
        ca_lnb = (const float*)d_in[22];
        mg_w1  = (const float*)d_in[23];
        mg_b1  = (const float*)d_in[24];
        mg_w2  = (const float*)d_in[25];
        mg_b2  = (const float*)d_in[26];
    }
    float* out = (float*)d_out;

    float* KV = (float*)sym_addr(g_KV);
    float* Qb = (float*)sym_addr(g_Q);
    float* Kb = (float*)sym_addr(g_K);
    float* Vb = (float*)sym_addr(g_V);
    float* AO = (float*)sym_addr(g_AO);
    float* FC = (float*)sym_addr(g_FC);
    float* SA = (float*)sym_addr(g_SA);
    float* H1 = (float*)sym_addr(g_H1);
    float* KC = (float*)sym_addr(g_KC);
    float* KH = (float*)sym_addr(g_KH);
    float* VH = (float*)sym_addr(g_VH);
    float* QH = (float*)sym_addr(g_QH);
    unsigned* WH = (unsigned*)sym_addr(g_WH);
    unsigned* WL = (unsigned*)sym_addr(g_WL);
    unsigned char* MK = (unsigned char*)sym_addr(g_mask8);

    const int SMEM_ATTN = SM_ATTN_U32 * 4;     // 206848 bytes
    cudaFuncSetAttribute(sa_attn_kernel, cudaFuncAttributeMaxDynamicSharedMemorySize, SMEM_ATTN);
    const int SMEM_GEMM = SM_GEMM_U32 * 4;     // 40960 bytes (2 CTAs/SM)
    cudaFuncSetAttribute(gemm_tc_kernel, cudaFuncAttributeMaxDynamicSharedMemorySize, SMEM_GEMM);

    detect_mask_kernel<<<1, 32>>>(maskraw);
    norm_mask_kernel<<<NROWS / 256, 256>>>(maskraw);

    // weight packing (tiny, once per launch)
    pack_w_kernel<<<(256 * 128 + 255) / 256, 256>>>(sa_wq,  256, 256, WH + WO_SAQ, WL + WO_SAQ);
    pack_w_kernel<<<(256 * 128 + 255) / 256, 256>>>(sa_wk,  256, 256, WH + WO_SAK, WL + WO_SAK);
    pack_w_kernel<<<(256 * 128 + 255) / 256, 256>>>(sa_wv,  256, 256, WH + WO_SAV, WL + WO_SAV);
    pack_w_kernel<<<(256 * 128 + 255) / 256, 256>>>(sa_fcw, 256, 256, WH + WO_SAF, WL + WO_SAF);
    pack_w_kernel<<<(256 * 192 + 255) / 256, 256>>>(ms_w1,  384, 256, WH + WO_MS1, WL + WO_MS1);
    pack_w_kernel<<<(256 * 128 + 255) / 256, 256>>>(ms_w2,  256, 256, WH + WO_MS2, WL + WO_MS2);
    pack_w_kernel<<<(256 * 128 + 255) / 256, 256>>>(ca_wq,  256, 256, WH + WO_CAQ, WL + WO_CAQ);
    pack_w_kernel<<<(256 * 128 + 255) / 256, 256>>>(ca_wk,  256, 256, WH + WO_CAK, WL + WO_CAK);
    pack_w_kernel<<<(256 * 128 + 255) / 256, 256>>>(ca_wv,  256, 256, WH + WO_CAV, WL + WO_CAV);

    concat_kv_kernel<<<ELEMS / 4 / 256, 256>>>(seq, seqt);

    dim3 g2(2, NROWS / 128);
    gemm_tc_kernel<<<g2, 256, SMEM_GEMM>>>(KV, 256, 256, KV, 256, WH + WO_SAQ, WL + WO_SAQ, 256, 256, nullptr, nullptr, 0, Qb);
    gemm_tc_kernel<<<g2, 256, SMEM_GEMM>>>(KV, 256, 256, KV, 256, WH + WO_SAK, WL + WO_SAK, 256, 256, nullptr, nullptr, 0, Kb);
    gemm_tc_kernel<<<g2, 256, SMEM_GEMM>>>(KV, 256, 256, KV, 256, WH + WO_SAV, WL + WO_SAV, 256, 256, nullptr, nullptr, 0, Vb);

    dim3 ga(2, BATCH);
    sa_attn_kernel<<<ga, 256, SMEM_ATTN>>>(Qb, Kb, Vb, MK, AO);

    gemm_tc_kernel<<<g2, 256, SMEM_GEMM>>>(AO, 256, 256, AO, 256, WH + WO_SAF, WL + WO_SAF, 256, 256, sa_fcb, KV, 0, FC);
    ln_kernel<<<NROWS / 8, 256>>>(FC, sa_lng, sa_lnb, SA);

    gemm_tc_kernel<<<g2, 256, SMEM_GEMM>>>(SA, 256, 256, seq, 128, WH + WO_MS1, WL + WO_MS1, 384, 256, ms_b1, nullptr, 1, H1);
    gemm_tc_kernel<<<g2, 256, SMEM_GEMM>>>(H1, 256, 256, H1, 256, WH + WO_MS2, WL + WO_MS2, 256, 256, ms_b2, nullptr, 0, KC);

    gemm_tc_kernel<<<g2, 256, SMEM_GEMM>>>(KC, 256, 256, KC, 256, WH + WO_CAK, WL + WO_CAK, 256, 256, nullptr, nullptr, 0, KH);
    gemm_tc_kernel<<<g2, 256, SMEM_GEMM>>>(KC, 256, 256, KC, 256, WH + WO_CAV, WL + WO_CAV, 256, 256, nullptr, nullptr, 0, VH);

    dim3 gq(2, BATCH / 128);
    gemm_tc_kernel<<<gq, 256, SMEM_GEMM>>>(src, 128, 128, srct, 128, WH + WO_CAQ, WL + WO_CAQ, 256, 256, nullptr, nullptr, 0, QH);

    ca_kernel<<<BATCH, 256>>>(QH, KH, VH, MK,
                              ca_fcw, ca_fcb, ca_lng, ca_lnb,
                              src, srct, mg_w1, mg_b1, mg_w2, mg_b2,
                              out, out + (long)BATCH * 128);
}

// round 13
// speedup vs baseline: 1.0433x; 1.0433x over previous
#include <cuda_runtime.h>
#include <cuda_bf16.h>
#include <math.h>

#define BATCH  1024
#define SEQN   128
#define DMODEL 256
#define NROWS  (BATCH*SEQN)            // 131072
#define ELEMS  (BATCH*SEQN*DMODEL)     // 33554432
#define SST    132

// bf16 GEMM smem layout, u32 units. Row stride = 20 u32 (32 bf16 + pad) = 80 B.
#define RSTR 20
#define UA_H 0
#define UA_L (128*RSTR)
#define UB_H (2*128*RSTR)
#define UB_L (3*128*RSTR)
#define SM_GEMM_U32 (4*128*RSTR)     // 10240 u32 = 40960 B

// sa_attn smem layout (u32 units). Row stride 68 u32.
#define QSTR 68
#define OQH 0
#define OQL (128*QSTR)
#define OKH (2*128*QSTR)
#define OKL (3*128*QSTR)
#define OPT (4*128*QSTR)
#define SM_ATTN_U32 (4*128*QSTR + 128*SST)   // 206848 B

// ---------------- scratch ----------------
__device__ float g_Q [ELEMS];
__device__ float g_K [ELEMS];
__device__ float g_V [ELEMS];
__device__ float g_AO[ELEMS];
__device__ float g_FC[ELEMS];
__device__ float g_SA[ELEMS];
__device__ float g_H1[ELEMS];
__device__ float g_KC[ELEMS];
__device__ float g_KH[ELEMS];
__device__ float g_VH[ELEMS];
__device__ float g_QH[BATCH*DMODEL];
__device__ unsigned char g_mask8[NROWS];
__device__ int g_mask_mode;

// ---------------- bf16 helpers ----------------
__device__ __forceinline__ unsigned pack_bf16x2(float lo, float hi) {
    unsigned r;
    asm("cvt.rn.bf16x2.f32 %0, %1, %2;" : "=r"(r) : "f"(hi), "f"(lo));
    return r;
}
__device__ __forceinline__ float lo_bf16f(unsigned u) { return __uint_as_float(u << 16); }
__device__ __forceinline__ float hi_bf16f(unsigned u) { return __uint_as_float(u & 0xFFFF0000u); }
__device__ __forceinline__ void split_pair(float f0, float f1, unsigned& h, unsigned& l) {
    h = pack_bf16x2(f0, f1);
    l = pack_bf16x2(f0 - lo_bf16f(h), f1 - hi_bf16f(h));
}
__device__ __forceinline__ void mma_bf16(float* d, const unsigned* a, const unsigned* b) {
    asm volatile(
        "mma.sync.aligned.m16n8k16.row.col.f32.bf16.bf16.f32 "
        "{%0,%1,%2,%3}, {%4,%5,%6,%7}, {%8,%9}, {%0,%1,%2,%3};\n"
        : "+f"(d[0]), "+f"(d[1]), "+f"(d[2]), "+f"(d[3])
        : "r"(a[0]), "r"(a[1]), "r"(a[2]), "r"(a[3]),
          "r"(b[0]), "r"(b[1]));
}

// ---------------- mask dtype detection + normalization ----------------
__global__ void detect_mask_kernel(const void* mask) {
    if (threadIdx.x == 0 && blockIdx.x == 0) {
        const unsigned* p = (const unsigned*)mask;
        int mode = 1;
        for (int i = 0; i < 1024; i++) {
            unsigned v = p[i];
            if (v == 0x3F800000u) { mode = 2; break; }
            if (v > 1u) { mode = 0; break; }
        }
        g_mask_mode = mode;
    }
}

__global__ __launch_bounds__(256) void norm_mask_kernel(const void* mask) {
    int i = blockIdx.x * 256 + threadIdx.x;
    if (i >= NROWS) return;
    int mode = g_mask_mode;
    unsigned char m;
    if (mode == 0)      m = (((const unsigned char*)mask)[i] != 0);
    else if (mode == 1) m = (((const int*)mask)[i] != 0);
    else                m = (((const float*)mask)[i] != 0.f);
    g_mask8[i] = m;
}

// ---------------- 3xBF16 tensor-core GEMM (R8/R10-proven compute loop) ----------------
// C[M,N] = concat(A1,A2)[M,Ktot] @ W[Ktot,N] (+bias)(+dual residual)(relu)
// BM=128, BN=128, BK=32; 256 thr; warps 4(m)x2(n); warp tile 32x64.
__global__ __launch_bounds__(256, 2) void gemm_tc_kernel(
    const float* __restrict__ A1, int K1, int lda1,
    const float* __restrict__ A2, int lda2,
    const float* __restrict__ W, int Ktot, int Ncols,
    const float* __restrict__ bias,
    const float* __restrict__ res1, int R1, int ldr1,   // residual cols [0,R1)
    const float* __restrict__ res2, int ldr2,           // residual cols [R1,..)
    int relu,
    float* __restrict__ C)
{
    extern __shared__ unsigned su[];
    unsigned* sAh = su + UA_H;
    unsigned* sAl = su + UA_L;
    unsigned* sBh = su + UB_H;
    unsigned* sBl = su + UB_L;

    const int tid  = threadIdx.x;
    const int warp = tid >> 5, lane = tid & 31;
    const int wm = warp & 3, wn = warp >> 2;
    const int group = lane >> 2, tig = lane & 3;
    const long m0 = (long)blockIdx.y * 128;
    const int  n0 = blockIdx.x * 128;
    const int wmb = wm * 32;
    const int wnb = wn * 64;

    float acc[2][8][4];
#pragma unroll
    for (int mi = 0; mi < 2; mi++)
#pragma unroll
        for (int ni = 0; ni < 8; ni++)
#pragma unroll
            for (int q = 0; q < 4; q++) acc[mi][ni][q] = 0.f;

    const int nk = Ktot / 32;

    for (int ck = 0; ck < nk; ck++) {
        const int k0 = ck * 32;
        if (ck > 0) __syncthreads();

#pragma unroll
        for (int i = 0; i < 4; i++) {
            int f4 = tid + i * 256;
            int row = f4 >> 3, c = (f4 & 7) * 4;
            const float* ap = (k0 + c < K1) ? (A1 + (m0 + row) * (long)lda1 + k0 + c)
                                            : (A2 + (m0 + row) * (long)lda2 + (k0 + c - K1));
            float4 v = *(const float4*)ap;
            unsigned h0, l0, h1, l1;
            split_pair(v.x, v.y, h0, l0);
            split_pair(v.z, v.w, h1, l1);
            int ui = row * RSTR + (c >> 1);
            *(uint2*)&sAh[ui] = make_uint2(h0, h1);
            *(uint2*)&sAl[ui] = make_uint2(l0, l1);
        }
#pragma unroll
        for (int i = 0; i < 4; i++) {
            int task = tid + i * 256;
            int n  = task & 127;
            int kq = task >> 7;
            const float* wp = W + (long)(k0 + kq * 4) * Ncols + n0 + n;
            float f0 = wp[0];
            float f1 = wp[Ncols];
            float f2 = wp[2 * Ncols];
            float f3 = wp[3 * Ncols];
            unsigned h0, l0, h1, l1;
            split_pair(f0, f1, h0, l0);
            split_pair(f2, f3, h1, l1);
            int ui = n * RSTR + kq * 2;
            *(uint2*)&sBh[ui] = make_uint2(h0, h1);
            *(uint2*)&sBl[ui] = make_uint2(l0, l1);
        }
        __syncthreads();

#pragma unroll
        for (int ks = 0; ks < 2; ks++) {
            const int kb8 = ks * 8;
            unsigned ah[2][4], al[2][4];
#pragma unroll
            for (int mi = 0; mi < 2; mi++) {
                int r = wmb + mi * 16 + group;
                int i0 = r * RSTR + kb8 + tig;
                int i1 = (r + 8) * RSTR + kb8 + tig;
                ah[mi][0] = sAh[i0];
                ah[mi][1] = sAh[i1];
                ah[mi][2] = sAh[i0 + 4];
                ah[mi][3] = sAh[i1 + 4];
                al[mi][0] = sAl[i0];
                al[mi][1] = sAl[i1];
                al[mi][2] = sAl[i0 + 4];
                al[mi][3] = sAl[i1 + 4];
            }
#pragma unroll
            for (int nt = 0; nt < 8; nt++) {
                int nrow = wnb + nt * 8 + group;
                int bi = nrow * RSTR + kb8 + tig;
                unsigned bh[2], bl[2];
                bh[0] = sBh[bi];
                bh[1] = sBh[bi + 4];
                bl[0] = sBl[bi];
                bl[1] = sBl[bi + 4];
#pragma unroll
                for (int mi = 0; mi < 2; mi++) {
                    mma_bf16(acc[mi][nt], ah[mi], bh);
                    mma_bf16(acc[mi][nt], al[mi], bh);
                    mma_bf16(acc[mi][nt], ah[mi], bl);
                }
            }
        }
    }

#pragma unroll
    for (int mi = 0; mi < 2; mi++) {
        long gm = m0 + wmb + mi * 16 + group;
#pragma unroll
        for (int ni = 0; ni < 8; ni++) {
            int gc = n0 + wnb + ni * 8 + 2 * tig;
            float v0 = acc[mi][ni][0], v1 = acc[mi][ni][1];
            float v2 = acc[mi][ni][2], v3 = acc[mi][ni][3];
            if (bias) {
                float b0 = bias[gc], b1 = bias[gc + 1];
                v0 += b0; v1 += b1; v2 += b0; v3 += b1;
            }
            if (res1) {
                const float* rp0 = (gc < R1) ? (res1 + gm * ldr1 + gc)
                                             : (res2 + gm * ldr2 + gc - R1);
                const float* rp1 = (gc < R1) ? (res1 + (gm + 8) * ldr1 + gc)
                                             : (res2 + (gm + 8) * ldr2 + gc - R1);
                float2 r0 = *(const float2*)rp0;
                float2 r1 = *(const float2*)rp1;
                v0 += r0.x; v1 += r0.y; v2 += r1.x; v3 += r1.y;
            }
            if (relu) {
                v0 = fmaxf(v0, 0.f); v1 = fmaxf(v1, 0.f);
                v2 = fmaxf(v2, 0.f); v3 = fmaxf(v3, 0.f);
            }
            *(float2*)(C + gm * Ncols + gc)       = make_float2(v0, v1);
            *(float2*)(C + (gm + 8) * Ncols + gc) = make_float2(v2, v3);
        }
    }
}

// ---------------- self-attention: full bf16 tensor-core (R10 proven) ----------------
__global__ __launch_bounds__(256) void sa_attn_kernel(
    const float* __restrict__ Q, const float* __restrict__ K, const float* __restrict__ V,
    const unsigned char* __restrict__ mask, float* __restrict__ O)
{
    extern __shared__ unsigned su[];
    float* sPt = (float*)(su + OPT);
    __shared__ unsigned char smask[128];

    const int h = blockIdx.x, b = blockIdx.y;
    const int tid = threadIdx.x;
    const int warp = tid >> 5, lane = tid & 31;
    const int group = lane >> 2, tig = lane & 3;
    const float* Qp = Q + ((long)b * SEQN) * DMODEL + h * 128;
    const float* Kp = K + ((long)b * SEQN) * DMODEL + h * 128;
    const float* Vp = V + ((long)b * SEQN) * DMODEL + h * 128;
    const float invs = 0.0883883476483184f;

    const int wm = warp & 3;
    const int wmb = wm * 32, wnb = (warp >> 2) * 64;

    if (tid < 128) smask[tid] = mask[(long)b * SEQN + tid];
    for (int idx = tid; idx < 128 * 32; idx += 256) {
        int r = idx >> 5;
        int c = (idx & 31) << 2;
        int ui = r * QSTR + (c >> 1);
        float4 qv = *(const float4*)(Qp + (long)r * DMODEL + c);
        qv.x *= invs; qv.y *= invs; qv.z *= invs; qv.w *= invs;
        unsigned h0, l0, h1, l1;
        split_pair(qv.x, qv.y, h0, l0);
        split_pair(qv.z, qv.w, h1, l1);
        *(uint2*)&su[OQH + ui] = make_uint2(h0, h1);
        *(uint2*)&su[OQL + ui] = make_uint2(l0, l1);
        float4 kv = *(const float4*)(Kp + (long)r * DMODEL + c);
        split_pair(kv.x, kv.y, h0, l0);
        split_pair(kv.z, kv.w, h1, l1);
        *(uint2*)&su[OKH + ui] = make_uint2(h0, h1);
        *(uint2*)&su[OKL + ui] = make_uint2(l0, l1);
    }
    __syncthreads();

    {
        float acc[2][8][4];
#pragma unroll
        for (int mi = 0; mi < 2; mi++)
#pragma unroll
            for (int ni = 0; ni < 8; ni++)
#pragma unroll
                for (int q = 0; q < 4; q++) acc[mi][ni][q] = 0.f;

#pragma unroll
        for (int ks = 0; ks < 8; ks++) {
            const int kb8 = ks * 8;
            unsigned ah[2][4], al[2][4];
#pragma unroll
            for (int mi = 0; mi < 2; mi++) {
                int r = wmb + mi * 16 + group;
                int i0 = r * QSTR + kb8 + tig;
                int i1 = (r + 8) * QSTR + kb8 + tig;
                ah[mi][0] = su[OQH + i0];
                ah[mi][1] = su[OQH + i1];
                ah[mi][2] = su[OQH + i0 + 4];
                ah[mi][3] = su[OQH + i1 + 4];
                al[mi][0] = su[OQL + i0];
                al[mi][1] = su[OQL + i1];
                al[mi][2] = su[OQL + i0 + 4];
                al[mi][3] = su[OQL + i1 + 4];
            }
#pragma unroll
            for (int nt = 0; nt < 8; nt++) {
                int nrow = wnb + nt * 8 + group;
                int bi = nrow * QSTR + kb8 + tig;
                unsigned bh[2], bl[2];
                bh[0] = su[OKH + bi];
                bh[1] = su[OKH + bi + 4];
                bl[0] = su[OKL + bi];
                bl[1] = su[OKL + bi + 4];
#pragma unroll
                for (int mi = 0; mi < 2; mi++) {
                    mma_bf16(acc[mi][nt], ah[mi], bh);
                    mma_bf16(acc[mi][nt], al[mi], bh);
                    mma_bf16(acc[mi][nt], ah[mi], bl);
                }
            }
        }
#pragma unroll
        for (int mi = 0; mi < 2; mi++) {
            int gm0 = wmb + mi * 16 + group;
#pragma unroll
            for (int ni = 0; ni < 8; ni++) {
                int gc0 = wnb + ni * 8 + 2 * tig;
                sPt[gc0 * SST + gm0]           = acc[mi][ni][0];
                sPt[(gc0 + 1) * SST + gm0]     = acc[mi][ni][1];
                sPt[gc0 * SST + gm0 + 8]       = acc[mi][ni][2];
                sPt[(gc0 + 1) * SST + gm0 + 8] = acc[mi][ni][3];
            }
        }
    }
    __syncthreads();

    for (int r = warp; r < 128; r += 8) {
        float vv[4];
        float mx = -1e30f;
#pragma unroll
        for (int q = 0; q < 4; q++) {
            int c = lane + q * 32;
            float s = sPt[c * SST + r];
            if (smask[c]) s = -1e10f;
            vv[q] = s; mx = fmaxf(mx, s);
        }
#pragma unroll
        for (int o = 16; o > 0; o >>= 1) mx = fmaxf(mx, __shfl_xor_sync(0xffffffffu, mx, o));
        float sum = 0.f;
#pragma unroll
        for (int q = 0; q < 4; q++) { vv[q] = expf(vv[q] - mx); sum += vv[q]; }
#pragma unroll
        for (int o = 16; o > 0; o >>= 1) sum += __shfl_xor_sync(0xffffffffu, sum, o);
        float rs = 1.f / sum;
#pragma unroll
        for (int q = 0; q < 4; q++) sPt[(lane + q * 32) * SST + r] = vv[q] * rs;
    }
    __syncthreads();

    for (int idx = tid; idx < 128 * 64; idx += 256) {
        int q = idx >> 6, kp = idx & 63;
        float p0 = sPt[(2 * kp) * SST + q];
        float p1 = sPt[(2 * kp + 1) * SST + q];
        unsigned hh, ll;
        split_pair(p0, p1, hh, ll);
        su[OQH + q * QSTR + kp] = hh;
        su[OQL + q * QSTR + kp] = ll;
    }
    for (int idx = tid; idx < 64 * 32; idx += 256) {
        int kplow = idx & 15;
        int rest  = idx >> 4;
        int c4 = rest & 31;
        int kp = (rest >> 5) * 16 + kplow;
        int c = c4 * 4;
        float4 v0 = *(const float4*)(Vp + (long)(2 * kp) * DMODEL + c);
        float4 v1 = *(const float4*)(Vp + (long)(2 * kp + 1) * DMODEL + c);
        unsigned hh, ll;
        split_pair(v0.x, v1.x, hh, ll);
        su[OKH + (c + 0) * QSTR + kp] = hh; su[OKL + (c + 0) * QSTR + kp] = ll;
        split_pair(v0.y, v1.y, hh, ll);
        su[OKH + (c + 1) * QSTR + kp] = hh; su[OKL + (c + 1) * QSTR + kp] = ll;
        split_pair(v0.z, v1.z, hh, ll);
        su[OKH + (c + 2) * QSTR + kp] = hh; su[OKL + (c + 2) * QSTR + kp] = ll;
        split_pair(v0.w, v1.w, hh, ll);
        su[OKH + (c + 3) * QSTR + kp] = hh; su[OKL + (c + 3) * QSTR + kp] = ll;
    }
    __syncthreads();

    {
        float acc[2][8][4];
#pragma unroll
        for (int mi = 0; mi < 2; mi++)
#pragma unroll
            for (int ni = 0; ni < 8; ni++)
#pragma unroll
                for (int q = 0; q < 4; q++) acc[mi][ni][q] = 0.f;

#pragma unroll
        for (int ks = 0; ks < 8; ks++) {
            const int kb8 = ks * 8;
            unsigned ah[2][4], al[2][4];
#pragma unroll
            for (int mi = 0; mi < 2; mi++) {
                int r = wmb + mi * 16 + group;
                int i0 = r * QSTR + kb8 + tig;
                int i1 = (r + 8) * QSTR + kb8 + tig;
                ah[mi][0] = su[OQH + i0];
                ah[mi][1] = su[OQH + i1];
                ah[mi][2] = su[OQH + i0 + 4];
                ah[mi][3] = su[OQH + i1 + 4];
                al[mi][0] = su[OQL + i0];
                al[mi][1] = su[OQL + i1];
                al[mi][2] = su[OQL + i0 + 4];
                al[mi][3] = su[OQL + i1 + 4];
            }
#pragma unroll
            for (int nt = 0; nt < 8; nt++) {
                int nrow = wnb + nt * 8 + group;
                int bi = nrow * QSTR + kb8 + tig;
                unsigned bh[2], bl[2];
                bh[0] = su[OKH + bi];
                bh[1] = su[OKH + bi + 4];
                bl[0] = su[OKL + bi];
                bl[1] = su[OKL + bi + 4];
#pragma unroll
                for (int mi = 0; mi < 2; mi++) {
                    mma_bf16(acc[mi][nt], ah[mi], bh);
                    mma_bf16(acc[mi][nt], al[mi], bh);
                    mma_bf16(acc[mi][nt], ah[mi], bl);
                }
            }
        }

        float* Op = O + ((long)b * SEQN) * DMODEL + h * 128;
#pragma unroll
        for (int mi = 0; mi < 2; mi++) {
            int gm = wmb + mi * 16 + group;
#pragma unroll
            for (int nt = 0; nt < 8; nt++) {
                int gc = wnb + nt * 8 + 2 * tig;
                *(float2*)(Op + (long)gm * DMODEL + gc)       = make_float2(acc[mi][nt][0], acc[mi][nt][1]);
                *(float2*)(Op + (long)(gm + 8) * DMODEL + gc) = make_float2(acc[mi][nt][2], acc[mi][nt][3]);
            }
        }
    }
}

// ---------------- LayerNorm over 256, warp per row ----------------
__global__ __launch_bounds__(256) void ln_kernel(
    const float* __restrict__ X, const float* __restrict__ gw,
    const float* __restrict__ bw, float* __restrict__ Y)
{
    long row = (long)blockIdx.x * 8 + (threadIdx.x >> 5);
    int lane = threadIdx.x & 31;
    const float* xp = X + row * 256 + lane * 8;
    float4 a = *(const float4*)xp;
    float4 b = *(const float4*)(xp + 4);
    float s = a.x + a.y + a.z + a.w + b.x + b.y + b.z + b.w;
#pragma unroll
    for (int o = 16; o > 0; o >>= 1) s += __shfl_xor_sync(0xffffffffu, s, o);
    float mean = s * 0.00390625f;
    float q = 0.f;
    q += (a.x - mean) * (a.x - mean); q += (a.y - mean) * (a.y - mean);
    q += (a.z - mean) * (a.z - mean); q += (a.w - mean) * (a.w - mean);
    q += (b.x - mean) * (b.x - mean); q += (b.y - mean) * (b.y - mean);
    q += (b.z - mean) * (b.z - mean); q += (b.w - mean) * (b.w - mean);
#pragma unroll
    for (int o = 16; o > 0; o >>= 1) q += __shfl_xor_sync(0xffffffffu, q, o);
    float rstd = rsqrtf(q * 0.00390625f + 1e-5f);
    int c = lane * 8;
    float4 g0 = *(const float4*)(gw + c), g1 = *(const float4*)(gw + c + 4);
    float4 b0 = *(const float4*)(bw + c), b1 = *(const float4*)(bw + c + 4);
    float4 o0, o1;
    o0.x = (a.x - mean) * rstd * g0.x + b0.x;
    o0.y = (a.y - mean) * rstd * g0.y + b0.y;
    o0.z = (a.z - mean) * rstd * g0.z + b0.z;
    o0.w = (a.w - mean) * rstd * g0.w + b0.w;
    o1.x = (b.x - mean) * rstd * g1.x + b1.x;
    o1.y = (b.y - mean) * rstd * g1.y + b1.y;
    o1.z = (b.z - mean) * rstd * g1.z + b1.z;
    o1.w = (b.w - mean) * rstd * g1.w + b1.w;
    *(float4*)(Y + row * 256 + c)     = o0;
    *(float4*)(Y + row * 256 + c + 4) = o1;
}

// ---------------- cross-attention + fc + LN + output MLP ----------------
__global__ __launch_bounds__(256) void ca_kernel(
    const float* __restrict__ QH, const float* __restrict__ KH, const float* __restrict__ VH,
    const unsigned char* __restrict__ mask,
    const float* __restrict__ fcw, const float* __restrict__ fcb,
    const float* __restrict__ lng, const float* __restrict__ lnb,
    const float* __restrict__ src, const float* __restrict__ srct,
    const float* __restrict__ w1, const float* __restrict__ b1,
    const float* __restrict__ w2, const float* __restrict__ b2,
    float* __restrict__ out_vec, float* __restrict__ out_attn)
{
    const int b = blockIdx.x;
    const int tid = threadIdx.x;
    __shared__ float s_q[256], s_p[256], s_o[256], s_y[256], s_h[128], s_red[16];

    s_q[tid] = QH[(long)b * 256 + tid];
    __syncthreads();

    const int h = tid >> 7, k = tid & 127;
    const int lane = tid & 31, warp = tid >> 5;

    const float* krow = KH + ((long)b * 128 + k) * 256 + h * 128;
    float s = 0.f;
#pragma unroll 8
    for (int d = 0; d < 128; d += 4) {
        float4 kv = *(const float4*)(krow + d);
        s += s_q[h * 128 + d + 0] * kv.x + s_q[h * 128 + d + 1] * kv.y
           + s_q[h * 128 + d + 2] * kv.z + s_q[h * 128 + d + 3] * kv.w;
    }
    s *= 0.0883883476483184f;
    if (mask[(long)b * 128 + k]) s = -1e10f;

    float mx = s;
#pragma unroll
    for (int o = 16; o > 0; o >>= 1) mx = fmaxf(mx, __shfl_xor_sync(0xffffffffu, mx, o));
    if (lane == 0) s_red[warp] = mx;
    __syncthreads();
    mx = fmaxf(fmaxf(s_red[h * 4 + 0], s_red[h * 4 + 1]),
               fmaxf(s_red[h * 4 + 2], s_red[h * 4 + 3]));
    float e = expf(s - mx);
    float sum = e;
#pragma unroll
    for (int o = 16; o > 0; o >>= 1) sum += __shfl_xor_sync(0xffffffffu, sum, o);
    if (lane == 0) s_red[8 + warp] = sum;
    __syncthreads();
    sum = s_red[8 + h * 4 + 0] + s_red[8 + h * 4 + 1] + s_red[8 + h * 4 + 2] + s_red[8 + h * 4 + 3];
    float p = e / sum;
    s_p[tid] = p;
    out_attn[((long)h * BATCH + b) * 128 + k] = p;
    __syncthreads();

    const int d = tid & 127;
    float o = 0.f;
#pragma unroll 8
    for (int kk = 0; kk < 128; kk++)
        o += s_p[h * 128 + kk] * VH[((long)b * 128 + kk) * 256 + h * 128 + d];
    s_o[tid] = o;
    __syncthreads();

    float y = fcb[tid];
    for (int i = 0; i < 256; i++) y += s_o[i] * fcw[i * 256 + tid];
    y += (tid < 128) ? src[(long)b * 128 + tid] : srct[(long)b * 128 + tid - 128];

    float t = y;
#pragma unroll
    for (int ofs = 16; ofs > 0; ofs >>= 1) t += __shfl_xor_sync(0xffffffffu, t, ofs);
    if (lane == 0) s_red[warp] = t;
    __syncthreads();
    float mean = (s_red[0] + s_red[1] + s_red[2] + s_red[3] +
                  s_red[4] + s_red[5] + s_red[6] + s_red[7]) * 0.00390625f;
    float dv = y - mean;
    t = dv * dv;
#pragma unroll
    for (int ofs = 16; ofs > 0; ofs >>= 1) t += __shfl_xor_sync(0xffffffffu, t, ofs);
    if (lane == 0) s_red[8 + warp] = t;
    __syncthreads();
    float var = (s_red[8] + s_red[9] + s_red[10] + s_red[11] +
                 s_red[12] + s_red[13] + s_red[14] + s_red[15]) * 0.00390625f;
    float rstd = rsqrtf(var + 1e-5f);
    s_y[tid] = dv * rstd * lng[tid] + lnb[tid];
    __syncthreads();

    if (tid < 128) {
        float hh = b1[tid];
        for (int i = 0; i < 256; i++) hh += s_y[i] * w1[i * 128 + tid];
        for (int i = 0; i < 128; i++) hh += src[(long)b * 128 + i] * w1[(256 + i) * 128 + tid];
        s_h[tid] = fmaxf(hh, 0.f);
    }
    __syncthreads();
    if (tid < 128) {
        float oo = b2[tid];
        for (int i = 0; i < 128; i++) oo += s_h[i] * w2[i * 128 + tid];
        out_vec[(long)b * 128 + tid] = oo;
    }
}

// ---------------- host ----------------
static void* sym_addr(const void* s) {
    void* p = nullptr;
    cudaGetSymbolAddress(&p, s);
    return p;
}

extern "C" void kernel_launch(void* const* d_in, const int* in_sizes, int n_in,
                              void* d_out, int out_size)
{
    const float* src   = (const float*)d_in[0];
    const float* srct  = (const float*)d_in[1];
    const float* seq   = (const float*)d_in[2];
    const float* seqt  = (const float*)d_in[3];
    const void*  maskraw = d_in[4];

    const float *sa_wq, *sa_wk, *sa_wv, *sa_fcw, *sa_fcb, *sa_lng, *sa_lnb;
    const float *ms_w1, *ms_b1, *ms_w2, *ms_b2;
    const float *ca_wq, *ca_wk, *ca_wv, *ca_fcw, *ca_fcb, *ca_lng, *ca_lnb;
    const float *mg_w1, *mg_b1, *mg_w2, *mg_b2;

    bool dict_order = (in_sizes[10] == 98304);
    if (dict_order) {
        sa_wq  = (const float*)d_in[5];
        sa_wk  = (const float*)d_in[6];
        sa_wv  = (const float*)d_in[7];
        sa_fcw = (const float*)d_in[8];
        sa_fcb = (const float*)d_in[9];
        ms_w1  = (const float*)d_in[10];
        ms_b1  = (const float*)d_in[11];
        ms_w2  = (const float*)d_in[12];
        ms_b2  = (const float*)d_in[13];
        ca_wq  = (const float*)d_in[14];
        ca_wk  = (const float*)d_in[15];
        ca_wv  = (const float*)d_in[16];
        ca_fcw = (const float*)d_in[17];
        ca_fcb = (const float*)d_in[18];
        mg_w1  = (const float*)d_in[19];
        mg_b1  = (const float*)d_in[20];
        mg_w2  = (const float*)d_in[21];
        mg_b2  = (const float*)d_in[22];
        sa_lng = (const float*)d_in[23];
        sa_lnb = (const float*)d_in[24];
        ca_lng = (const float*)d_in[25];
        ca_lnb = (const float*)d_in[26];
    } else {
        sa_wq  = (const float*)d_in[5];
        sa_wk  = (const float*)d_in[6];
        sa_wv  = (const float*)d_in[7];
        sa_fcw = (const float*)d_in[8];
        sa_fcb = (const float*)d_in[9];
        sa_lng = (const float*)d_in[10];
        sa_lnb = (const float*)d_in[11];
        ms_w1  = (const float*)d_in[12];
        ms_b1  = (const float*)d_in[13];
        ms_w2  = (const float*)d_in[14];
        ms_b2  = (const float*)d_in[15];
        ca_wq  = (const float*)d_in[16];
        ca_wk  = (const float*)d_in[17];
        ca_wv  = (const float*)d_in[18];
        ca_fcw = (const float*)d_in[19];
        ca_fcb = (const float*)d_in[20];
        ca_lng = (const float*)d_in[21];
        ca_lnb = (const float*)d_in[22];
        mg_w1  = (const float*)d_in[23];
        mg_b1  = (const float*)d_in[24];
        mg_w2  = (const float*)d_in[25];
        mg_b2  = (const float*)d_in[26];
    }
    float* out = (float*)d_out;

    float* Qb = (float*)sym_addr(g_Q);
    float* Kb = (float*)sym_addr(g_K);
    float* Vb = (float*)sym_addr(g_V);
    float* AO = (float*)sym_addr(g_AO);
    float* FC = (float*)sym_addr(g_FC);
    float* SA = (float*)sym_addr(g_SA);
    float* H1 = (float*)sym_addr(g_H1);
    float* KC = (float*)sym_addr(g_KC);
    float* KH = (float*)sym_addr(g_KH);
    float* VH = (float*)sym_addr(g_VH);
    float* QH = (float*)sym_addr(g_QH);
    unsigned char* MK = (unsigned char*)sym_addr(g_mask8);

    const int SMEM_ATTN = SM_ATTN_U32 * 4;     // 206848 bytes
    cudaFuncSetAttribute(sa_attn_kernel, cudaFuncAttributeMaxDynamicSharedMemorySize, SMEM_ATTN);
    const int SMEM_GEMM = SM_GEMM_U32 * 4;     // 40960 bytes (2 CTAs/SM)
    cudaFuncSetAttribute(gemm_tc_kernel, cudaFuncAttributeMaxDynamicSharedMemorySize, SMEM_GEMM);

    detect_mask_kernel<<<1, 32>>>(maskraw);
    norm_mask_kernel<<<NROWS / 256, 256>>>(maskraw);

    dim3 g2(2, NROWS / 128);
    // QKV projections: A = concat(seq, seqt) read directly (no concat kernel)
    gemm_tc_kernel<<<g2, 256, SMEM_GEMM>>>(seq, 128, 128, seqt, 128, sa_wq, 256, 256, nullptr, nullptr, 0, 0, nullptr, 0, 0, Qb);
    gemm_tc_kernel<<<g2, 256, SMEM_GEMM>>>(seq, 128, 128, seqt, 128, sa_wk, 256, 256, nullptr, nullptr, 0, 0, nullptr, 0, 0, Kb);
    gemm_tc_kernel<<<g2, 256, SMEM_GEMM>>>(seq, 128, 128, seqt, 128, sa_wv, 256, 256, nullptr, nullptr, 0, 0, nullptr, 0, 0, Vb);

    dim3 ga(2, BATCH);
    sa_attn_kernel<<<ga, 256, SMEM_ATTN>>>(Qb, Kb, Vb, MK, AO);

    // fc: residual = concat(seq, seqt) split at col 128
    gemm_tc_kernel<<<g2, 256, SMEM_GEMM>>>(AO, 256, 256, AO, 256, sa_fcw, 256, 256, sa_fcb, seq, 128, 128, seqt, 128, 0, FC);
    ln_kernel<<<NROWS / 8, 256>>>(FC, sa_lng, sa_lnb, SA);

    gemm_tc_kernel<<<g2, 256, SMEM_GEMM>>>(SA, 256, 256, seq, 128, ms_w1, 384, 256, ms_b1, nullptr, 0, 0, nullptr, 0, 1, H1);
    gemm_tc_kernel<<<g2, 256, SMEM_GEMM>>>(H1, 256, 256, H1, 256, ms_w2, 256, 256, ms_b2, nullptr, 0, 0, nullptr, 0, 0, KC);

    gemm_tc_kernel<<<g2, 256, SMEM_GEMM>>>(KC, 256, 256, KC, 256, ca_wk, 256, 256, nullptr, nullptr, 0, 0, nullptr, 0, 0, KH);
    gemm_tc_kernel<<<g2, 256, SMEM_GEMM>>>(KC, 256, 256, KC, 256, ca_wv, 256, 256, nullptr, nullptr, 0, 0, nullptr, 0, 0, VH);

    dim3 gq(2, BATCH / 128);
    gemm_tc_kernel<<<gq, 256, SMEM_GEMM>>>(src, 128, 128, srct, 128, ca_wq, 256, 256, nullptr, nullptr, 0, 0, nullptr, 0, 0, QH);

    ca_kernel<<<BATCH, 256>>>(QH, KH, VH, MK,
                              ca_fcw, ca_fcb, ca_lng, ca_lnb,
                              src, srct, mg_w1, mg_b1, mg_w2, mg_b2,
                              out, out + (long)BATCH * 128);
}

// round 14
// speedup vs baseline: 1.1624x; 1.1141x over previous
#include <cuda_runtime.h>
#include <cuda_bf16.h>
#include <math.h>

#define BATCH  1024
#define SEQN   128
#define DMODEL 256
#define NROWS  (BATCH*SEQN)            // 131072
#define ELEMS  (BATCH*SEQN*DMODEL)     // 33554432
#define SST    132

// bf16 GEMM smem layout, u32 units. Row stride = 20 u32 (32 bf16 + pad) = 80 B.
#define RSTR 20
#define UA_H 0
#define UA_L (128*RSTR)
#define UB_H (2*128*RSTR)
#define UB_L (3*128*RSTR)
#define SM_GEMM_U32 (4*128*RSTR)     // 10240 u32 = 40960 B

// sa_attn smem layout (u32 units). Row stride 68 u32.
#define QSTR 68
#define OQH 0
#define OQL (128*QSTR)
#define OKH (2*128*QSTR)
#define OKL (3*128*QSTR)
#define OPT (4*128*QSTR)
#define SM_ATTN_U32 (4*128*QSTR + 128*SST)   // 206848 B

// ---------------- scratch ----------------
__device__ float g_KV[ELEMS];
__device__ float g_Q [ELEMS];
__device__ float g_K [ELEMS];
__device__ float g_V [ELEMS];
__device__ float g_AO[ELEMS];
__device__ float g_FC[ELEMS];
__device__ float g_SA[ELEMS];
__device__ float g_H1[ELEMS];
__device__ float g_KC[ELEMS];
__device__ float g_KH[ELEMS];
__device__ float g_VH[ELEMS];
__device__ float g_QH[BATCH*DMODEL];
__device__ unsigned char g_mask8[NROWS];
__device__ int g_mask_mode;

// ---------------- bf16 helpers ----------------
__device__ __forceinline__ unsigned pack_bf16x2(float lo, float hi) {
    unsigned r;
    asm("cvt.rn.bf16x2.f32 %0, %1, %2;" : "=r"(r) : "f"(hi), "f"(lo));
    return r;
}
__device__ __forceinline__ float lo_bf16f(unsigned u) { return __uint_as_float(u << 16); }
__device__ __forceinline__ float hi_bf16f(unsigned u) { return __uint_as_float(u & 0xFFFF0000u); }
__device__ __forceinline__ void split_pair(float f0, float f1, unsigned& h, unsigned& l) {
    h = pack_bf16x2(f0, f1);
    l = pack_bf16x2(f0 - lo_bf16f(h), f1 - hi_bf16f(h));
}
__device__ __forceinline__ void mma_bf16(float* d, const unsigned* a, const unsigned* b) {
    asm volatile(
        "mma.sync.aligned.m16n8k16.row.col.f32.bf16.bf16.f32 "
        "{%0,%1,%2,%3}, {%4,%5,%6,%7}, {%8,%9}, {%0,%1,%2,%3};\n"
        : "+f"(d[0]), "+f"(d[1]), "+f"(d[2]), "+f"(d[3])
        : "r"(a[0]), "r"(a[1]), "r"(a[2]), "r"(a[3]),
          "r"(b[0]), "r"(b[1]));
}

// ---------------- mask dtype detection + normalization ----------------
__global__ void detect_mask_kernel(const void* mask) {
    if (threadIdx.x == 0 && blockIdx.x == 0) {
        const unsigned* p = (const unsigned*)mask;
        int mode = 1;
        for (int i = 0; i < 1024; i++) {
            unsigned v = p[i];
            if (v == 0x3F800000u) { mode = 2; break; }
            if (v > 1u) { mode = 0; break; }
        }
        g_mask_mode = mode;
    }
}

__global__ __launch_bounds__(256) void norm_mask_kernel(const void* mask) {
    int i = blockIdx.x * 256 + threadIdx.x;
    if (i >= NROWS) return;
    int mode = g_mask_mode;
    unsigned char m;
    if (mode == 0)      m = (((const unsigned char*)mask)[i] != 0);
    else if (mode == 1) m = (((const int*)mask)[i] != 0);
    else                m = (((const float*)mask)[i] != 0.f);
    g_mask8[i] = m;
}

// ---------------- concat([seq, seq_t], -1) -> KV ----------------
__global__ __launch_bounds__(256) void concat_kv_kernel(
    const float* __restrict__ seq, const float* __restrict__ seqt)
{
    long i4 = (long)blockIdx.x * 256 + threadIdx.x;
    if (i4 >= (long)ELEMS / 4) return;
    long row = i4 >> 6;
    int  c4  = (int)(i4 & 63);
    float4 v;
    if (c4 < 32) v = ((const float4*)(seq  + row * 128))[c4];
    else         v = ((const float4*)(seqt + row * 128))[c4 - 32];
    ((float4*)(g_KV + row * 256))[c4] = v;
}

// ---------------- 3xBF16 tensor-core GEMM (R8/R10-proven, UNTOUCHED) ----------------
__global__ __launch_bounds__(256, 2) void gemm_tc_kernel(
    const float* __restrict__ A1, int K1, int lda1,
    const float* __restrict__ A2, int lda2,
    const float* __restrict__ W, int Ktot, int Ncols,
    const float* __restrict__ bias,
    const float* __restrict__ res,
    int relu,
    float* __restrict__ C)
{
    extern __shared__ unsigned su[];
    unsigned* sAh = su + UA_H;
    unsigned* sAl = su + UA_L;
    unsigned* sBh = su + UB_H;
    unsigned* sBl = su + UB_L;

    const int tid  = threadIdx.x;
    const int warp = tid >> 5, lane = tid & 31;
    const int wm = warp & 3, wn = warp >> 2;
    const int group = lane >> 2, tig = lane & 3;
    const long m0 = (long)blockIdx.y * 128;
    const int  n0 = blockIdx.x * 128;
    const int wmb = wm * 32;
    const int wnb = wn * 64;

    float acc[2][8][4];
#pragma unroll
    for (int mi = 0; mi < 2; mi++)
#pragma unroll
        for (int ni = 0; ni < 8; ni++)
#pragma unroll
            for (int q = 0; q < 4; q++) acc[mi][ni][q] = 0.f;

    const int nk = Ktot / 32;

    for (int ck = 0; ck < nk; ck++) {
        const int k0 = ck * 32;
        if (ck > 0) __syncthreads();

#pragma unroll
        for (int i = 0; i < 4; i++) {
            int f4 = tid + i * 256;
            int row = f4 >> 3, c = (f4 & 7) * 4;
            const float* ap = (k0 < K1) ? (A1 + (m0 + row) * (long)lda1 + k0 + c)
                                        : (A2 + (m0 + row) * (long)lda2 + (k0 - K1) + c);
            float4 v = *(const float4*)ap;
            unsigned h0, l0, h1, l1;
            split_pair(v.x, v.y, h0, l0);
            split_pair(v.z, v.w, h1, l1);
            int ui = row * RSTR + (c >> 1);
            *(uint2*)&sAh[ui] = make_uint2(h0, h1);
            *(uint2*)&sAl[ui] = make_uint2(l0, l1);
        }
#pragma unroll
        for (int i = 0; i < 4; i++) {
            int task = tid + i * 256;
            int n  = task & 127;
            int kq = task >> 7;
            const float* wp = W + (long)(k0 + kq * 4) * Ncols + n0 + n;
            float f0 = wp[0];
            float f1 = wp[Ncols];
            float f2 = wp[2 * Ncols];
            float f3 = wp[3 * Ncols];
            unsigned h0, l0, h1, l1;
            split_pair(f0, f1, h0, l0);
            split_pair(f2, f3, h1, l1);
            int ui = n * RSTR + kq * 2;
            *(uint2*)&sBh[ui] = make_uint2(h0, h1);
            *(uint2*)&sBl[ui] = make_uint2(l0, l1);
        }
        __syncthreads();

#pragma unroll
        for (int ks = 0; ks < 2; ks++) {
            const int kb8 = ks * 8;
            unsigned ah[2][4], al[2][4];
#pragma unroll
            for (int mi = 0; mi < 2; mi++) {
                int r = wmb + mi * 16 + group;
                int i0 = r * RSTR + kb8 + tig;
                int i1 = (r + 8) * RSTR + kb8 + tig;
                ah[mi][0] = sAh[i0];
                ah[mi][1] = sAh[i1];
                ah[mi][2] = sAh[i0 + 4];
                ah[mi][3] = sAh[i1 + 4];
                al[mi][0] = sAl[i0];
                al[mi][1] = sAl[i1];
                al[mi][2] = sAl[i0 + 4];
                al[mi][3] = sAl[i1 + 4];
            }
#pragma unroll
            for (int nt = 0; nt < 8; nt++) {
                int nrow = wnb + nt * 8 + group;
                int bi = nrow * RSTR + kb8 + tig;
                unsigned bh[2], bl[2];
                bh[0] = sBh[bi];
                bh[1] = sBh[bi + 4];
                bl[0] = sBl[bi];
                bl[1] = sBl[bi + 4];
#pragma unroll
                for (int mi = 0; mi < 2; mi++) {
                    mma_bf16(acc[mi][nt], ah[mi], bh);
                    mma_bf16(acc[mi][nt], al[mi], bh);
                    mma_bf16(acc[mi][nt], ah[mi], bl);
                }
            }
        }
    }

#pragma unroll
    for (int mi = 0; mi < 2; mi++) {
        long gm = m0 + wmb + mi * 16 + group;
#pragma unroll
        for (int ni = 0; ni < 8; ni++) {
            int gc = n0 + wnb + ni * 8 + 2 * tig;
            float v0 = acc[mi][ni][0], v1 = acc[mi][ni][1];
            float v2 = acc[mi][ni][2], v3 = acc[mi][ni][3];
            if (bias) {
                float b0 = bias[gc], b1 = bias[gc + 1];
                v0 += b0; v1 += b1; v2 += b0; v3 += b1;
            }
            if (res) {
                float2 r0 = *(const float2*)(res + gm * Ncols + gc);
                float2 r1 = *(const float2*)(res + (gm + 8) * Ncols + gc);
                v0 += r0.x; v1 += r0.y; v2 += r1.x; v3 += r1.y;
            }
            if (relu) {
                v0 = fmaxf(v0, 0.f); v1 = fmaxf(v1, 0.f);
                v2 = fmaxf(v2, 0.f); v3 = fmaxf(v3, 0.f);
            }
            *(float2*)(C + gm * Ncols + gc)       = make_float2(v0, v1);
            *(float2*)(C + (gm + 8) * Ncols + gc) = make_float2(v2, v3);
        }
    }
}

// ---------------- self-attention: full bf16 tensor-core, 512 threads (16 warps) ----------------
// warps 4(m) x 4(n); warp tile 32x32 per phase.
__global__ __launch_bounds__(512) void sa_attn_kernel(
    const float* __restrict__ Q, const float* __restrict__ K, const float* __restrict__ V,
    const unsigned char* __restrict__ mask, float* __restrict__ O)
{
    extern __shared__ unsigned su[];
    float* sPt = (float*)(su + OPT);
    __shared__ unsigned char smask[128];

    const int h = blockIdx.x, b = blockIdx.y;
    const int tid = threadIdx.x;
    const int warp = tid >> 5, lane = tid & 31;
    const int group = lane >> 2, tig = lane & 3;
    const float* Qp = Q + ((long)b * SEQN) * DMODEL + h * 128;
    const float* Kp = K + ((long)b * SEQN) * DMODEL + h * 128;
    const float* Vp = V + ((long)b * SEQN) * DMODEL + h * 128;
    const float invs = 0.0883883476483184f;

    const int wm = warp & 3;
    const int wn = warp >> 2;           // 0..3
    const int wmb = wm * 32, wnb = wn * 32;

    if (tid < 128) smask[tid] = mask[(long)b * SEQN + tid];
    // ---- load + pack Q(scaled), K -> hi/lo [row][kp] ----
    for (int idx = tid; idx < 128 * 32; idx += 512) {
        int r = idx >> 5;
        int c = (idx & 31) << 2;
        int ui = r * QSTR + (c >> 1);
        float4 qv = *(const float4*)(Qp + (long)r * DMODEL + c);
        qv.x *= invs; qv.y *= invs; qv.z *= invs; qv.w *= invs;
        unsigned h0, l0, h1, l1;
        split_pair(qv.x, qv.y, h0, l0);
        split_pair(qv.z, qv.w, h1, l1);
        *(uint2*)&su[OQH + ui] = make_uint2(h0, h1);
        *(uint2*)&su[OQL + ui] = make_uint2(l0, l1);
        float4 kv = *(const float4*)(Kp + (long)r * DMODEL + c);
        split_pair(kv.x, kv.y, h0, l0);
        split_pair(kv.z, kv.w, h1, l1);
        *(uint2*)&su[OKH + ui] = make_uint2(h0, h1);
        *(uint2*)&su[OKL + ui] = make_uint2(l0, l1);
    }
    __syncthreads();

    // ---- S = Qs · K^T ----
    {
        float acc[2][4][4];
#pragma unroll
        for (int mi = 0; mi < 2; mi++)
#pragma unroll
            for (int ni = 0; ni < 4; ni++)
#pragma unroll
                for (int q = 0; q < 4; q++) acc[mi][ni][q] = 0.f;

#pragma unroll
        for (int ks = 0; ks < 8; ks++) {
            const int kb8 = ks * 8;
            unsigned ah[2][4], al[2][4];
#pragma unroll
            for (int mi = 0; mi < 2; mi++) {
                int r = wmb + mi * 16 + group;
                int i0 = r * QSTR + kb8 + tig;
                int i1 = (r + 8) * QSTR + kb8 + tig;
                ah[mi][0] = su[OQH + i0];
                ah[mi][1] = su[OQH + i1];
                ah[mi][2] = su[OQH + i0 + 4];
                ah[mi][3] = su[OQH + i1 + 4];
                al[mi][0] = su[OQL + i0];
                al[mi][1] = su[OQL + i1];
                al[mi][2] = su[OQL + i0 + 4];
                al[mi][3] = su[OQL + i1 + 4];
            }
#pragma unroll
            for (int nt = 0; nt < 4; nt++) {
                int nrow = wnb + nt * 8 + group;
                int bi = nrow * QSTR + kb8 + tig;
                unsigned bh[2], bl[2];
                bh[0] = su[OKH + bi];
                bh[1] = su[OKH + bi + 4];
                bl[0] = su[OKL + bi];
                bl[1] = su[OKL + bi + 4];
#pragma unroll
                for (int mi = 0; mi < 2; mi++) {
                    mma_bf16(acc[mi][nt], ah[mi], bh);
                    mma_bf16(acc[mi][nt], al[mi], bh);
                    mma_bf16(acc[mi][nt], ah[mi], bl);
                }
            }
        }
#pragma unroll
        for (int mi = 0; mi < 2; mi++) {
            int gm0 = wmb + mi * 16 + group;
#pragma unroll
            for (int ni = 0; ni < 4; ni++) {
                int gc0 = wnb + ni * 8 + 2 * tig;
                sPt[gc0 * SST + gm0]           = acc[mi][ni][0];
                sPt[(gc0 + 1) * SST + gm0]     = acc[mi][ni][1];
                sPt[gc0 * SST + gm0 + 8]       = acc[mi][ni][2];
                sPt[(gc0 + 1) * SST + gm0 + 8] = acc[mi][ni][3];
            }
        }
    }
    __syncthreads();

    // ---- softmax over keys (per query row r) ----
    for (int r = warp; r < 128; r += 16) {
        float vv[4];
        float mx = -1e30f;
#pragma unroll
        for (int q = 0; q < 4; q++) {
            int c = lane + q * 32;
            float s = sPt[c * SST + r];
            if (smask[c]) s = -1e10f;
            vv[q] = s; mx = fmaxf(mx, s);
        }
#pragma unroll
        for (int o = 16; o > 0; o >>= 1) mx = fmaxf(mx, __shfl_xor_sync(0xffffffffu, mx, o));
        float sum = 0.f;
#pragma unroll
        for (int q = 0; q < 4; q++) { vv[q] = expf(vv[q] - mx); sum += vv[q]; }
#pragma unroll
        for (int o = 16; o > 0; o >>= 1) sum += __shfl_xor_sync(0xffffffffu, sum, o);
        float rs = 1.f / sum;
#pragma unroll
        for (int q = 0; q < 4; q++) sPt[(lane + q * 32) * SST + r] = vv[q] * rs;
    }
    __syncthreads();

    // ---- pack P [q][kp] into Q region; pack V^T [d][kp] into K region ----
    for (int idx = tid; idx < 128 * 64; idx += 512) {
        int q = idx >> 6, kp = idx & 63;
        float p0 = sPt[(2 * kp) * SST + q];
        float p1 = sPt[(2 * kp + 1) * SST + q];
        unsigned hh, ll;
        split_pair(p0, p1, hh, ll);
        su[OQH + q * QSTR + kp] = hh;
        su[OQL + q * QSTR + kp] = ll;
    }
    for (int idx = tid; idx < 64 * 32; idx += 512) {
        int kplow = idx & 15;
        int rest  = idx >> 4;
        int c4 = rest & 31;
        int kp = (rest >> 5) * 16 + kplow;
        int c = c4 * 4;
        float4 v0 = *(const float4*)(Vp + (long)(2 * kp) * DMODEL + c);
        float4 v1 = *(const float4*)(Vp + (long)(2 * kp + 1) * DMODEL + c);
        unsigned hh, ll;
        split_pair(v0.x, v1.x, hh, ll);
        su[OKH + (c + 0) * QSTR + kp] = hh; su[OKL + (c + 0) * QSTR + kp] = ll;
        split_pair(v0.y, v1.y, hh, ll);
        su[OKH + (c + 1) * QSTR + kp] = hh; su[OKL + (c + 1) * QSTR + kp] = ll;
        split_pair(v0.z, v1.z, hh, ll);
        su[OKH + (c + 2) * QSTR + kp] = hh; su[OKL + (c + 2) * QSTR + kp] = ll;
        split_pair(v0.w, v1.w, hh, ll);
        su[OKH + (c + 3) * QSTR + kp] = hh; su[OKL + (c + 3) * QSTR + kp] = ll;
    }
    __syncthreads();

    // ---- O = P · V ----
    {
        float acc[2][4][4];
#pragma unroll
        for (int mi = 0; mi < 2; mi++)
#pragma unroll
            for (int ni = 0; ni < 4; ni++)
#pragma unroll
                for (int q = 0; q < 4; q++) acc[mi][ni][q] = 0.f;

#pragma unroll
        for (int ks = 0; ks < 8; ks++) {
            const int kb8 = ks * 8;
            unsigned ah[2][4], al[2][4];
#pragma unroll
            for (int mi = 0; mi < 2; mi++) {
                int r = wmb + mi * 16 + group;
                int i0 = r * QSTR + kb8 + tig;
                int i1 = (r + 8) * QSTR + kb8 + tig;
                ah[mi][0] = su[OQH + i0];
                ah[mi][1] = su[OQH + i1];
                ah[mi][2] = su[OQH + i0 + 4];
                ah[mi][3] = su[OQH + i1 + 4];
                al[mi][0] = su[OQL + i0];
                al[mi][1] = su[OQL + i1];
                al[mi][2] = su[OQL + i0 + 4];
                al[mi][3] = su[OQL + i1 + 4];
            }
#pragma unroll
            for (int nt = 0; nt < 4; nt++) {
                int nrow = wnb + nt * 8 + group;
                int bi = nrow * QSTR + kb8 + tig;
                unsigned bh[2], bl[2];
                bh[0] = su[OKH + bi];
                bh[1] = su[OKH + bi + 4];
                bl[0] = su[OKL + bi];
                bl[1] = su[OKL + bi + 4];
#pragma unroll
                for (int mi = 0; mi < 2; mi++) {
                    mma_bf16(acc[mi][nt], ah[mi], bh);
                    mma_bf16(acc[mi][nt], al[mi], bh);
                    mma_bf16(acc[mi][nt], ah[mi], bl);
                }
            }
        }

        float* Op = O + ((long)b * SEQN) * DMODEL + h * 128;
#pragma unroll
        for (int mi = 0; mi < 2; mi++) {
            int gm = wmb + mi * 16 + group;
#pragma unroll
            for (int nt = 0; nt < 4; nt++) {
                int gc = wnb + nt * 8 + 2 * tig;
                *(float2*)(Op + (long)gm * DMODEL + gc)       = make_float2(acc[mi][nt][0], acc[mi][nt][1]);
                *(float2*)(Op + (long)(gm + 8) * DMODEL + gc) = make_float2(acc[mi][nt][2], acc[mi][nt][3]);
            }
        }
    }
}

// ---------------- LayerNorm over 256, warp per row ----------------
__global__ __launch_bounds__(256) void ln_kernel(
    const float* __restrict__ X, const float* __restrict__ gw,
    const float* __restrict__ bw, float* __restrict__ Y)
{
    long row = (long)blockIdx.x * 8 + (threadIdx.x >> 5);
    int lane = threadIdx.x & 31;
    const float* xp = X + row * 256 + lane * 8;
    float4 a = *(const float4*)xp;
    float4 b = *(const float4*)(xp + 4);
    float s = a.x + a.y + a.z + a.w + b.x + b.y + b.z + b.w;
#pragma unroll
    for (int o = 16; o > 0; o >>= 1) s += __shfl_xor_sync(0xffffffffu, s, o);
    float mean = s * 0.00390625f;
    float q = 0.f;
    q += (a.x - mean) * (a.x - mean); q += (a.y - mean) * (a.y - mean);
    q += (a.z - mean) * (a.z - mean); q += (a.w - mean) * (a.w - mean);
    q += (b.x - mean) * (b.x - mean); q += (b.y - mean) * (b.y - mean);
    q += (b.z - mean) * (b.z - mean); q += (b.w - mean) * (b.w - mean);
#pragma unroll
    for (int o = 16; o > 0; o >>= 1) q += __shfl_xor_sync(0xffffffffu, q, o);
    float rstd = rsqrtf(q * 0.00390625f + 1e-5f);
    int c = lane * 8;
    float4 g0 = *(const float4*)(gw + c), g1 = *(const float4*)(gw + c + 4);
    float4 b0 = *(const float4*)(bw + c), b1 = *(const float4*)(bw + c + 4);
    float4 o0, o1;
    o0.x = (a.x - mean) * rstd * g0.x + b0.x;
    o0.y = (a.y - mean) * rstd * g0.y + b0.y;
    o0.z = (a.z - mean) * rstd * g0.z + b0.z;
    o0.w = (a.w - mean) * rstd * g0.w + b0.w;
    o1.x = (b.x - mean) * rstd * g1.x + b1.x;
    o1.y = (b.y - mean) * rstd * g1.y + b1.y;
    o1.z = (b.z - mean) * rstd * g1.z + b1.z;
    o1.w = (b.w - mean) * rstd * g1.w + b1.w;
    *(float4*)(Y + row * 256 + c)     = o0;
    *(float4*)(Y + row * 256 + c + 4) = o1;
}

// ---------------- cross-attention + fc + LN + output MLP ----------------
__global__ __launch_bounds__(256) void ca_kernel(
    const float* __restrict__ QH, const float* __restrict__ KH, const float* __restrict__ VH,
    const unsigned char* __restrict__ mask,
    const float* __restrict__ fcw, const float* __restrict__ fcb,
    const float* __restrict__ lng, const float* __restrict__ lnb,
    const float* __restrict__ src, const float* __restrict__ srct,
    const float* __restrict__ w1, const float* __restrict__ b1,
    const float* __restrict__ w2, const float* __restrict__ b2,
    float* __restrict__ out_vec, float* __restrict__ out_attn)
{
    const int b = blockIdx.x;
    const int tid = threadIdx.x;
    __shared__ float s_q[256], s_p[256], s_o[256], s_y[256], s_h[128], s_red[16];

    s_q[tid] = QH[(long)b * 256 + tid];
    __syncthreads();

    const int h = tid >> 7, k = tid & 127;
    const int lane = tid & 31, warp = tid >> 5;

    const float* krow = KH + ((long)b * 128 + k) * 256 + h * 128;
    float s = 0.f;
#pragma unroll 8
    for (int d = 0; d < 128; d += 4) {
        float4 kv = *(const float4*)(krow + d);
        s += s_q[h * 128 + d + 0] * kv.x + s_q[h * 128 + d + 1] * kv.y
           + s_q[h * 128 + d + 2] * kv.z + s_q[h * 128 + d + 3] * kv.w;
    }
    s *= 0.0883883476483184f;
    if (mask[(long)b * 128 + k]) s = -1e10f;

    float mx = s;
#pragma unroll
    for (int o = 16; o > 0; o >>= 1) mx = fmaxf(mx, __shfl_xor_sync(0xffffffffu, mx, o));
    if (lane == 0) s_red[warp] = mx;
    __syncthreads();
    mx = fmaxf(fmaxf(s_red[h * 4 + 0], s_red[h * 4 + 1]),
               fmaxf(s_red[h * 4 + 2], s_red[h * 4 + 3]));
    float e = expf(s - mx);
    float sum = e;
#pragma unroll
    for (int o = 16; o > 0; o >>= 1) sum += __shfl_xor_sync(0xffffffffu, sum, o);
    if (lane == 0) s_red[8 + warp] = sum;
    __syncthreads();
    sum = s_red[8 + h * 4 + 0] + s_red[8 + h * 4 + 1] + s_red[8 + h * 4 + 2] + s_red[8 + h * 4 + 3];
    float p = e / sum;
    s_p[tid] = p;
    out_attn[((long)h * BATCH + b) * 128 + k] = p;
    __syncthreads();

    const int d = tid & 127;
    float o = 0.f;
#pragma unroll 8
    for (int kk = 0; kk < 128; kk++)
        o += s_p[h * 128 + kk] * VH[((long)b * 128 + kk) * 256 + h * 128 + d];
    s_o[tid] = o;
    __syncthreads();

    float y = fcb[tid];
    for (int i = 0; i < 256; i++) y += s_o[i] * fcw[i * 256 + tid];
    y += (tid < 128) ? src[(long)b * 128 + tid] : srct[(long)b * 128 + tid - 128];

    float t = y;
#pragma unroll
    for (int ofs = 16; ofs > 0; ofs >>= 1) t += __shfl_xor_sync(0xffffffffu, t, ofs);
    if (lane == 0) s_red[warp] = t;
    __syncthreads();
    float mean = (s_red[0] + s_red[1] + s_red[2] + s_red[3] +
                  s_red[4] + s_red[5] + s_red[6] + s_red[7]) * 0.00390625f;
    float dv = y - mean;
    t = dv * dv;
#pragma unroll
    for (int ofs = 16; ofs > 0; ofs >>= 1) t += __shfl_xor_sync(0xffffffffu, t, ofs);
    if (lane == 0) s_red[8 + warp] = t;
    __syncthreads();
    float var = (s_red[8] + s_red[9] + s_red[10] + s_red[11] +
                 s_red[12] + s_red[13] + s_red[14] + s_red[15]) * 0.00390625f;
    float rstd = rsqrtf(var + 1e-5f);
    s_y[tid] = dv * rstd * lng[tid] + lnb[tid];
    __syncthreads();

    if (tid < 128) {
        float hh = b1[tid];
        for (int i = 0; i < 256; i++) hh += s_y[i] * w1[i * 128 + tid];
        for (int i = 0; i < 128; i++) hh += src[(long)b * 128 + i] * w1[(256 + i) * 128 + tid];
        s_h[tid] = fmaxf(hh, 0.f);
    }
    __syncthreads();
    if (tid < 128) {
        float oo = b2[tid];
        for (int i = 0; i < 128; i++) oo += s_h[i] * w2[i * 128 + tid];
        out_vec[(long)b * 128 + tid] = oo;
    }
}

// ---------------- host ----------------
static void* sym_addr(const void* s) {
    void* p = nullptr;
    cudaGetSymbolAddress(&p, s);
    return p;
}

extern "C" void kernel_launch(void* const* d_in, const int* in_sizes, int n_in,
                              void* d_out, int out_size)
{
    const float* src   = (const float*)d_in[0];
    const float* srct  = (const float*)d_in[1];
    const float* seq   = (const float*)d_in[2];
    const float* seqt  = (const float*)d_in[3];
    const void*  maskraw = d_in[4];

    const float *sa_wq, *sa_wk, *sa_wv, *sa_fcw, *sa_fcb, *sa_lng, *sa_lnb;
    const float *ms_w1, *ms_b1, *ms_w2, *ms_b2;
    const float *ca_wq, *ca_wk, *ca_wv, *ca_fcw, *ca_fcb, *ca_lng, *ca_lnb;
    const float *mg_w1, *mg_b1, *mg_w2, *mg_b2;

    bool dict_order = (in_sizes[10] == 98304);
    if (dict_order) {
        sa_wq  = (const float*)d_in[5];
        sa_wk  = (const float*)d_in[6];
        sa_wv  = (const float*)d_in[7];
        sa_fcw = (const float*)d_in[8];
        sa_fcb = (const float*)d_in[9];
        ms_w1  = (const float*)d_in[10];
        ms_b1  = (const float*)d_in[11];
        ms_w2  = (const float*)d_in[12];
        ms_b2  = (const float*)d_in[13];
        ca_wq  = (const float*)d_in[14];
        ca_wk  = (const float*)d_in[15];
        ca_wv  = (const float*)d_in[16];
        ca_fcw = (const float*)d_in[17];
        ca_fcb = (const float*)d_in[18];
        mg_w1  = (const float*)d_in[19];
        mg_b1  = (const float*)d_in[20];
        mg_w2  = (const float*)d_in[21];
        mg_b2  = (const float*)d_in[22];
        sa_lng = (const float*)d_in[23];
        sa_lnb = (const float*)d_in[24];
        ca_lng = (const float*)d_in[25];
        ca_lnb = (const float*)d_in[26];
    } else {
        sa_wq  = (const float*)d_in[5];
        sa_wk  = (const float*)d_in[6];
        sa_wv  = (const float*)d_in[7];
        sa_fcw = (const float*)d_in[8];
        sa_fcb = (const float*)d_in[9];
        sa_lng = (const float*)d_in[10];
        sa_lnb = (const float*)d_in[11];
        ms_w1  = (const float*)d_in[12];
        ms_b1  = (const float*)d_in[13];
        ms_w2  = (const float*)d_in[14];
        ms_b2  = (const float*)d_in[15];
        ca_wq  = (const float*)d_in[16];
        ca_wk  = (const float*)d_in[17];
        ca_wv  = (const float*)d_in[18];
        ca_fcw = (const float*)d_in[19];
        ca_fcb = (const float*)d_in[20];
        ca_lng = (const float*)d_in[21];
        ca_lnb = (const float*)d_in[22];
        mg_w1  = (const float*)d_in[23];
        mg_b1  = (const float*)d_in[24];
        mg_w2  = (const float*)d_in[25];
        mg_b2  = (const float*)d_in[26];
    }
    float* out = (float*)d_out;

    float* KV = (float*)sym_addr(g_KV);
    float* Qb = (float*)sym_addr(g_Q);
    float* Kb = (float*)sym_addr(g_K);
    float* Vb = (float*)sym_addr(g_V);
    float* AO = (float*)sym_addr(g_AO);
    float* FC = (float*)sym_addr(g_FC);
    float* SA = (float*)sym_addr(g_SA);
    float* H1 = (float*)sym_addr(g_H1);
    float* KC = (float*)sym_addr(g_KC);
    float* KH = (float*)sym_addr(g_KH);
    float* VH = (float*)sym_addr(g_VH);
    float* QH = (float*)sym_addr(g_QH);
    unsigned char* MK = (unsigned char*)sym_addr(g_mask8);

    const int SMEM_ATTN = SM_ATTN_U32 * 4;     // 206848 bytes
    cudaFuncSetAttribute(sa_attn_kernel, cudaFuncAttributeMaxDynamicSharedMemorySize, SMEM_ATTN);
    const int SMEM_GEMM = SM_GEMM_U32 * 4;     // 40960 bytes (2 CTAs/SM)
    cudaFuncSetAttribute(gemm_tc_kernel, cudaFuncAttributeMaxDynamicSharedMemorySize, SMEM_GEMM);

    detect_mask_kernel<<<1, 32>>>(maskraw);
    norm_mask_kernel<<<NROWS / 256, 256>>>(maskraw);

    concat_kv_kernel<<<ELEMS / 4 / 256, 256>>>(seq, seqt);

    dim3 g2(2, NROWS / 128);
    gemm_tc_kernel<<<g2, 256, SMEM_GEMM>>>(KV, 256, 256, KV, 256, sa_wq, 256, 256, nullptr, nullptr, 0, Qb);
    gemm_tc_kernel<<<g2, 256, SMEM_GEMM>>>(KV, 256, 256, KV, 256, sa_wk, 256, 256, nullptr, nullptr, 0, Kb);
    gemm_tc_kernel<<<g2, 256, SMEM_GEMM>>>(KV, 256, 256, KV, 256, sa_wv, 256, 256, nullptr, nullptr, 0, Vb);

    dim3 ga(2, BATCH);
    sa_attn_kernel<<<ga, 512, SMEM_ATTN>>>(Qb, Kb, Vb, MK, AO);

    gemm_tc_kernel<<<g2, 256, SMEM_GEMM>>>(AO, 256, 256, AO, 256, sa_fcw, 256, 256, sa_fcb, KV, 0, FC);
    ln_kernel<<<NROWS / 8, 256>>>(FC, sa_lng, sa_lnb, SA);

    gemm_tc_kernel<<<g2, 256, SMEM_GEMM>>>(SA, 256, 256, seq, 128, ms_w1, 384, 256, ms_b1, nullptr, 1, H1);
    gemm_tc_kernel<<<g2, 256, SMEM_GEMM>>>(H1, 256, 256, H1, 256, ms_w2, 256, 256, ms_b2, nullptr, 0, KC);

    gemm_tc_kernel<<<g2, 256, SMEM_GEMM>>>(KC, 256, 256, KC, 256, ca_wk, 256, 256, nullptr, nullptr, 0, KH);
    gemm_tc_kernel<<<g2, 256, SMEM_GEMM>>>(KC, 256, 256, KC, 256, ca_wv, 256, 256, nullptr, nullptr, 0, VH);

    dim3 gq(2, BATCH / 128);
    gemm_tc_kernel<<<gq, 256, SMEM_GEMM>>>(src, 128, 128, srct, 128, ca_wq, 256, 256, nullptr, nullptr, 0, QH);

    ca_kernel<<<BATCH, 256>>>(QH, KH, VH, MK,
                              ca_fcw, ca_fcb, ca_lng, ca_lnb,
                              src, srct, mg_w1, mg_b1, mg_w2, mg_b2,
                              out, out + (long)BATCH * 128);
}

// round 15
// speedup vs baseline: 1.1677x; 1.0046x over previous
#include <cuda_runtime.h>
#include <cuda_bf16.h>
#include <math.h>

#define BATCH  1024
#define SEQN   128
#define DMODEL 256
#define NROWS  (BATCH*SEQN)            // 131072
#define ELEMS  (BATCH*SEQN*DMODEL)     // 33554432
#define SST    132

// bf16 GEMM smem layout, u32 units. Row stride = 20 u32 (32 bf16 + pad) = 80 B.
#define RSTR 20
#define UA_H 0
#define UA_L (128*RSTR)
#define UB_H (2*128*RSTR)
#define UB_L (3*128*RSTR)
#define SM_GEMM_U32 (4*128*RSTR)     // 10240 u32 = 40960 B

// sa_attn smem layout (u32 units). Row stride 68 u32.
#define QSTR 68
#define OQH 0
#define OQL (128*QSTR)
#define OKH (2*128*QSTR)
#define OKL (3*128*QSTR)
#define OPT (4*128*QSTR)
#define SM_ATTN_U32 (4*128*QSTR + 128*SST)   // 206848 B

// ---------------- scratch ----------------
__device__ float g_KV[ELEMS];
__device__ float g_Q [ELEMS];
__device__ float g_K [ELEMS];
__device__ float g_V [ELEMS];
__device__ float g_AO[ELEMS];
__device__ float g_FC[ELEMS];
__device__ float g_SA[ELEMS];
__device__ float g_H1[ELEMS];
__device__ float g_KC[ELEMS];
__device__ float g_KH[ELEMS];
__device__ float g_VH[ELEMS];
__device__ float g_QH[BATCH*DMODEL];
__device__ unsigned char g_mask8[NROWS];
__device__ int g_mask_mode;

// ---------------- bf16 helpers ----------------
__device__ __forceinline__ unsigned pack_bf16x2(float lo, float hi) {
    unsigned r;
    asm("cvt.rn.bf16x2.f32 %0, %1, %2;" : "=r"(r) : "f"(hi), "f"(lo));
    return r;
}
__device__ __forceinline__ float lo_bf16f(unsigned u) { return __uint_as_float(u << 16); }
__device__ __forceinline__ float hi_bf16f(unsigned u) { return __uint_as_float(u & 0xFFFF0000u); }
__device__ __forceinline__ void split_pair(float f0, float f1, unsigned& h, unsigned& l) {
    h = pack_bf16x2(f0, f1);
    l = pack_bf16x2(f0 - lo_bf16f(h), f1 - hi_bf16f(h));
}
__device__ __forceinline__ void mma_bf16(float* d, const unsigned* a, const unsigned* b) {
    asm volatile(
        "mma.sync.aligned.m16n8k16.row.col.f32.bf16.bf16.f32 "
        "{%0,%1,%2,%3}, {%4,%5,%6,%7}, {%8,%9}, {%0,%1,%2,%3};\n"
        : "+f"(d[0]), "+f"(d[1]), "+f"(d[2]), "+f"(d[3])
        : "r"(a[0]), "r"(a[1]), "r"(a[2]), "r"(a[3]),
          "r"(b[0]), "r"(b[1]));
}

// ---------------- mask dtype detection + normalization ----------------
__global__ void detect_mask_kernel(const void* mask) {
    if (threadIdx.x == 0 && blockIdx.x == 0) {
        const unsigned* p = (const unsigned*)mask;
        int mode = 1;
        for (int i = 0; i < 1024; i++) {
            unsigned v = p[i];
            if (v == 0x3F800000u) { mode = 2; break; }
            if (v > 1u) { mode = 0; break; }
        }
        g_mask_mode = mode;
    }
}

__global__ __launch_bounds__(256) void norm_mask_kernel(const void* mask) {
    int i = blockIdx.x * 256 + threadIdx.x;
    if (i >= NROWS) return;
    int mode = g_mask_mode;
    unsigned char m;
    if (mode == 0)      m = (((const unsigned char*)mask)[i] != 0);
    else if (mode == 1) m = (((const int*)mask)[i] != 0);
    else                m = (((const float*)mask)[i] != 0.f);
    g_mask8[i] = m;
}

// ---------------- concat([seq, seq_t], -1) -> KV ----------------
__global__ __launch_bounds__(256) void concat_kv_kernel(
    const float* __restrict__ seq, const float* __restrict__ seqt)
{
    long i4 = (long)blockIdx.x * 256 + threadIdx.x;
    if (i4 >= (long)ELEMS / 4) return;
    long row = i4 >> 6;
    int  c4  = (int)(i4 & 63);
    float4 v;
    if (c4 < 32) v = ((const float4*)(seq  + row * 128))[c4];
    else         v = ((const float4*)(seqt + row * 128))[c4 - 32];
    ((float4*)(g_KV + row * 256))[c4] = v;
}

// ---------------- 3xBF16 tensor-core GEMM (R8/R10-proven, UNTOUCHED) ----------------
__global__ __launch_bounds__(256, 2) void gemm_tc_kernel(
    const float* __restrict__ A1, int K1, int lda1,
    const float* __restrict__ A2, int lda2,
    const float* __restrict__ W, int Ktot, int Ncols,
    const float* __restrict__ bias,
    const float* __restrict__ res,
    int relu,
    float* __restrict__ C)
{
    extern __shared__ unsigned su[];
    unsigned* sAh = su + UA_H;
    unsigned* sAl = su + UA_L;
    unsigned* sBh = su + UB_H;
    unsigned* sBl = su + UB_L;

    const int tid  = threadIdx.x;
    const int warp = tid >> 5, lane = tid & 31;
    const int wm = warp & 3, wn = warp >> 2;
    const int group = lane >> 2, tig = lane & 3;
    const long m0 = (long)blockIdx.y * 128;
    const int  n0 = blockIdx.x * 128;
    const int wmb = wm * 32;
    const int wnb = wn * 64;

    float acc[2][8][4];
#pragma unroll
    for (int mi = 0; mi < 2; mi++)
#pragma unroll
        for (int ni = 0; ni < 8; ni++)
#pragma unroll
            for (int q = 0; q < 4; q++) acc[mi][ni][q] = 0.f;

    const int nk = Ktot / 32;

    for (int ck = 0; ck < nk; ck++) {
        const int k0 = ck * 32;
        if (ck > 0) __syncthreads();

#pragma unroll
        for (int i = 0; i < 4; i++) {
            int f4 = tid + i * 256;
            int row = f4 >> 3, c = (f4 & 7) * 4;
            const float* ap = (k0 < K1) ? (A1 + (m0 + row) * (long)lda1 + k0 + c)
                                        : (A2 + (m0 + row) * (long)lda2 + (k0 - K1) + c);
            float4 v = *(const float4*)ap;
            unsigned h0, l0, h1, l1;
            split_pair(v.x, v.y, h0, l0);
            split_pair(v.z, v.w, h1, l1);
            int ui = row * RSTR + (c >> 1);
            *(uint2*)&sAh[ui] = make_uint2(h0, h1);
            *(uint2*)&sAl[ui] = make_uint2(l0, l1);
        }
#pragma unroll
        for (int i = 0; i < 4; i++) {
            int task = tid + i * 256;
            int n  = task & 127;
            int kq = task >> 7;
            const float* wp = W + (long)(k0 + kq * 4) * Ncols + n0 + n;
            float f0 = wp[0];
            float f1 = wp[Ncols];
            float f2 = wp[2 * Ncols];
            float f3 = wp[3 * Ncols];
            unsigned h0, l0, h1, l1;
            split_pair(f0, f1, h0, l0);
            split_pair(f2, f3, h1, l1);
            int ui = n * RSTR + kq * 2;
            *(uint2*)&sBh[ui] = make_uint2(h0, h1);
            *(uint2*)&sBl[ui] = make_uint2(l0, l1);
        }
        __syncthreads();

#pragma unroll
        for (int ks = 0; ks < 2; ks++) {
            const int kb8 = ks * 8;
            unsigned ah[2][4], al[2][4];
#pragma unroll
            for (int mi = 0; mi < 2; mi++) {
                int r = wmb + mi * 16 + group;
                int i0 = r * RSTR + kb8 + tig;
                int i1 = (r + 8) * RSTR + kb8 + tig;
                ah[mi][0] = sAh[i0];
                ah[mi][1] = sAh[i1];
                ah[mi][2] = sAh[i0 + 4];
                ah[mi][3] = sAh[i1 + 4];
                al[mi][0] = sAl[i0];
                al[mi][1] = sAl[i1];
                al[mi][2] = sAl[i0 + 4];
                al[mi][3] = sAl[i1 + 4];
            }
#pragma unroll
            for (int nt = 0; nt < 8; nt++) {
                int nrow = wnb + nt * 8 + group;
                int bi = nrow * RSTR + kb8 + tig;
                unsigned bh[2], bl[2];
                bh[0] = sBh[bi];
                bh[1] = sBh[bi + 4];
                bl[0] = sBl[bi];
                bl[1] = sBl[bi + 4];
#pragma unroll
                for (int mi = 0; mi < 2; mi++) {
                    mma_bf16(acc[mi][nt], ah[mi], bh);
                    mma_bf16(acc[mi][nt], al[mi], bh);
                    mma_bf16(acc[mi][nt], ah[mi], bl);
                }
            }
        }
    }

#pragma unroll
    for (int mi = 0; mi < 2; mi++) {
        long gm = m0 + wmb + mi * 16 + group;
#pragma unroll
        for (int ni = 0; ni < 8; ni++) {
            int gc = n0 + wnb + ni * 8 + 2 * tig;
            float v0 = acc[mi][ni][0], v1 = acc[mi][ni][1];
            float v2 = acc[mi][ni][2], v3 = acc[mi][ni][3];
            if (bias) {
                float b0 = bias[gc], b1 = bias[gc + 1];
                v0 += b0; v1 += b1; v2 += b0; v3 += b1;
            }
            if (res) {
                float2 r0 = *(const float2*)(res + gm * Ncols + gc);
                float2 r1 = *(const float2*)(res + (gm + 8) * Ncols + gc);
                v0 += r0.x; v1 += r0.y; v2 += r1.x; v3 += r1.y;
            }
            if (relu) {
                v0 = fmaxf(v0, 0.f); v1 = fmaxf(v1, 0.f);
                v2 = fmaxf(v2, 0.f); v3 = fmaxf(v3, 0.f);
            }
            *(float2*)(C + gm * Ncols + gc)       = make_float2(v0, v1);
            *(float2*)(C + (gm + 8) * Ncols + gc) = make_float2(v2, v3);
        }
    }
}

// ---------------- self-attention: full bf16 tensor-core, 512 threads (16 warps) ----------------
// warps 4(m) x 4(n); warp tile 32x32 per phase.
__global__ __launch_bounds__(512) void sa_attn_kernel(
    const float* __restrict__ Q, const float* __restrict__ K, const float* __restrict__ V,
    const unsigned char* __restrict__ mask, float* __restrict__ O)
{
    extern __shared__ unsigned su[];
    float* sPt = (float*)(su + OPT);
    __shared__ unsigned char smask[128];

    const int h = blockIdx.x, b = blockIdx.y;
    const int tid = threadIdx.x;
    const int warp = tid >> 5, lane = tid & 31;
    const int group = lane >> 2, tig = lane & 3;
    const float* Qp = Q + ((long)b * SEQN) * DMODEL + h * 128;
    const float* Kp = K + ((long)b * SEQN) * DMODEL + h * 128;
    const float* Vp = V + ((long)b * SEQN) * DMODEL + h * 128;
    const float invs = 0.0883883476483184f;

    const int wm = warp & 3;
    const int wn = warp >> 2;           // 0..3
    const int wmb = wm * 32, wnb = wn * 32;

    if (tid < 128) smask[tid] = mask[(long)b * SEQN + tid];
    // ---- load + pack Q(scaled), K -> hi/lo [row][kp] ----
    for (int idx = tid; idx < 128 * 32; idx += 512) {
        int r = idx >> 5;
        int c = (idx & 31) << 2;
        int ui = r * QSTR + (c >> 1);
        float4 qv = *(const float4*)(Qp + (long)r * DMODEL + c);
        qv.x *= invs; qv.y *= invs; qv.z *= invs; qv.w *= invs;
        unsigned h0, l0, h1, l1;
        split_pair(qv.x, qv.y, h0, l0);
        split_pair(qv.z, qv.w, h1, l1);
        *(uint2*)&su[OQH + ui] = make_uint2(h0, h1);
        *(uint2*)&su[OQL + ui] = make_uint2(l0, l1);
        float4 kv = *(const float4*)(Kp + (long)r * DMODEL + c);
        split_pair(kv.x, kv.y, h0, l0);
        split_pair(kv.z, kv.w, h1, l1);
        *(uint2*)&su[OKH + ui] = make_uint2(h0, h1);
        *(uint2*)&su[OKL + ui] = make_uint2(l0, l1);
    }
    __syncthreads();

    // ---- S = Qs · K^T ----
    {
        float acc[2][4][4];
#pragma unroll
        for (int mi = 0; mi < 2; mi++)
#pragma unroll
            for (int ni = 0; ni < 4; ni++)
#pragma unroll
                for (int q = 0; q < 4; q++) acc[mi][ni][q] = 0.f;

#pragma unroll
        for (int ks = 0; ks < 8; ks++) {
            const int kb8 = ks * 8;
            unsigned ah[2][4], al[2][4];
#pragma unroll
            for (int mi = 0; mi < 2; mi++) {
                int r = wmb + mi * 16 + group;
                int i0 = r * QSTR + kb8 + tig;
                int i1 = (r + 8) * QSTR + kb8 + tig;
                ah[mi][0] = su[OQH + i0];
                ah[mi][1] = su[OQH + i1];
                ah[mi][2] = su[OQH + i0 + 4];
                ah[mi][3] = su[OQH + i1 + 4];
                al[mi][0] = su[OQL + i0];
                al[mi][1] = su[OQL + i1];
                al[mi][2] = su[OQL + i0 + 4];
                al[mi][3] = su[OQL + i1 + 4];
            }
#pragma unroll
            for (int nt = 0; nt < 4; nt++) {
                int nrow = wnb + nt * 8 + group;
                int bi = nrow * QSTR + kb8 + tig;
                unsigned bh[2], bl[2];
                bh[0] = su[OKH + bi];
                bh[1] = su[OKH + bi + 4];
                bl[0] = su[OKL + bi];
                bl[1] = su[OKL + bi + 4];
#pragma unroll
                for (int mi = 0; mi < 2; mi++) {
                    mma_bf16(acc[mi][nt], ah[mi], bh);
                    mma_bf16(acc[mi][nt], al[mi], bh);
                    mma_bf16(acc[mi][nt], ah[mi], bl);
                }
            }
        }
#pragma unroll
        for (int mi = 0; mi < 2; mi++) {
            int gm0 = wmb + mi * 16 + group;
#pragma unroll
            for (int ni = 0; ni < 4; ni++) {
                int gc0 = wnb + ni * 8 + 2 * tig;
                sPt[gc0 * SST + gm0]           = acc[mi][ni][0];
                sPt[(gc0 + 1) * SST + gm0]     = acc[mi][ni][1];
                sPt[gc0 * SST + gm0 + 8]       = acc[mi][ni][2];
                sPt[(gc0 + 1) * SST + gm0 + 8] = acc[mi][ni][3];
            }
        }
    }
    __syncthreads();

    // ---- softmax over keys (per query row r) ----
    for (int r = warp; r < 128; r += 16) {
        float vv[4];
        float mx = -1e30f;
#pragma unroll
        for (int q = 0; q < 4; q++) {
            int c = lane + q * 32;
            float s = sPt[c * SST + r];
            if (smask[c]) s = -1e10f;
            vv[q] = s; mx = fmaxf(mx, s);
        }
#pragma unroll
        for (int o = 16; o > 0; o >>= 1) mx = fmaxf(mx, __shfl_xor_sync(0xffffffffu, mx, o));
        float sum = 0.f;
#pragma unroll
        for (int q = 0; q < 4; q++) { vv[q] = expf(vv[q] - mx); sum += vv[q]; }
#pragma unroll
        for (int o = 16; o > 0; o >>= 1) sum += __shfl_xor_sync(0xffffffffu, sum, o);
        float rs = 1.f / sum;
#pragma unroll
        for (int q = 0; q < 4; q++) sPt[(lane + q * 32) * SST + r] = vv[q] * rs;
    }
    __syncthreads();

    // ---- pack P [q][kp] into Q region; pack V^T [d][kp] into K region ----
    for (int idx = tid; idx < 128 * 64; idx += 512) {
        int q = idx >> 6, kp = idx & 63;
        float p0 = sPt[(2 * kp) * SST + q];
        float p1 = sPt[(2 * kp + 1) * SST + q];
        unsigned hh, ll;
        split_pair(p0, p1, hh, ll);
        su[OQH + q * QSTR + kp] = hh;
        su[OQL + q * QSTR + kp] = ll;
    }
    for (int idx = tid; idx < 64 * 32; idx += 512) {
        int kplow = idx & 15;
        int rest  = idx >> 4;
        int c4 = rest & 31;
        int kp = (rest >> 5) * 16 + kplow;
        int c = c4 * 4;
        float4 v0 = *(const float4*)(Vp + (long)(2 * kp) * DMODEL + c);
        float4 v1 = *(const float4*)(Vp + (long)(2 * kp + 1) * DMODEL + c);
        unsigned hh, ll;
        split_pair(v0.x, v1.x, hh, ll);
        su[OKH + (c + 0) * QSTR + kp] = hh; su[OKL + (c + 0) * QSTR + kp] = ll;
        split_pair(v0.y, v1.y, hh, ll);
        su[OKH + (c + 1) * QSTR + kp] = hh; su[OKL + (c + 1) * QSTR + kp] = ll;
        split_pair(v0.z, v1.z, hh, ll);
        su[OKH + (c + 2) * QSTR + kp] = hh; su[OKL + (c + 2) * QSTR + kp] = ll;
        split_pair(v0.w, v1.w, hh, ll);
        su[OKH + (c + 3) * QSTR + kp] = hh; su[OKL + (c + 3) * QSTR + kp] = ll;
    }
    __syncthreads();

    // ---- O = P · V ----
    {
        float acc[2][4][4];
#pragma unroll
        for (int mi = 0; mi < 2; mi++)
#pragma unroll
            for (int ni = 0; ni < 4; ni++)
#pragma unroll
                for (int q = 0; q < 4; q++) acc[mi][ni][q] = 0.f;

#pragma unroll
        for (int ks = 0; ks < 8; ks++) {
            const int kb8 = ks * 8;
            unsigned ah[2][4], al[2][4];
#pragma unroll
            for (int mi = 0; mi < 2; mi++) {
                int r = wmb + mi * 16 + group;
                int i0 = r * QSTR + kb8 + tig;
                int i1 = (r + 8) * QSTR + kb8 + tig;
                ah[mi][0] = su[OQH + i0];
                ah[mi][1] = su[OQH + i1];
                ah[mi][2] = su[OQH + i0 + 4];
                ah[mi][3] = su[OQH + i1 + 4];
                al[mi][0] = su[OQL + i0];
                al[mi][1] = su[OQL + i1];
                al[mi][2] = su[OQL + i0 + 4];
                al[mi][3] = su[OQL + i1 + 4];
            }
#pragma unroll
            for (int nt = 0; nt < 4; nt++) {
                int nrow = wnb + nt * 8 + group;
                int bi = nrow * QSTR + kb8 + tig;
                unsigned bh[2], bl[2];
                bh[0] = su[OKH + bi];
                bh[1] = su[OKH + bi + 4];
                bl[0] = su[OKL + bi];
                bl[1] = su[OKL + bi + 4];
#pragma unroll
                for (int mi = 0; mi < 2; mi++) {
                    mma_bf16(acc[mi][nt], ah[mi], bh);
                    mma_bf16(acc[mi][nt], al[mi], bh);
                    mma_bf16(acc[mi][nt], ah[mi], bl);
                }
            }
        }

        float* Op = O + ((long)b * SEQN) * DMODEL + h * 128;
#pragma unroll
        for (int mi = 0; mi < 2; mi++) {
            int gm = wmb + mi * 16 + group;
#pragma unroll
            for (int nt = 0; nt < 4; nt++) {
                int gc = wnb + nt * 8 + 2 * tig;
                *(float2*)(Op + (long)gm * DMODEL + gc)       = make_float2(acc[mi][nt][0], acc[mi][nt][1]);
                *(float2*)(Op + (long)(gm + 8) * DMODEL + gc) = make_float2(acc[mi][nt][2], acc[mi][nt][3]);
            }
        }
    }
}

// ---------------- LayerNorm over 256, warp per row ----------------
__global__ __launch_bounds__(256) void ln_kernel(
    const float* __restrict__ X, const float* __restrict__ gw,
    const float* __restrict__ bw, float* __restrict__ Y)
{
    long row = (long)blockIdx.x * 8 + (threadIdx.x >> 5);
    int lane = threadIdx.x & 31;
    const float* xp = X + row * 256 + lane * 8;
    float4 a = *(const float4*)xp;
    float4 b = *(const float4*)(xp + 4);
    float s = a.x + a.y + a.z + a.w + b.x + b.y + b.z + b.w;
#pragma unroll
    for (int o = 16; o > 0; o >>= 1) s += __shfl_xor_sync(0xffffffffu, s, o);
    float mean = s * 0.00390625f;
    float q = 0.f;
    q += (a.x - mean) * (a.x - mean); q += (a.y - mean) * (a.y - mean);
    q += (a.z - mean) * (a.z - mean); q += (a.w - mean) * (a.w - mean);
    q += (b.x - mean) * (b.x - mean); q += (b.y - mean) * (b.y - mean);
    q += (b.z - mean) * (b.z - mean); q += (b.w - mean) * (b.w - mean);
#pragma unroll
    for (int o = 16; o > 0; o >>= 1) q += __shfl_xor_sync(0xffffffffu, q, o);
    float rstd = rsqrtf(q * 0.00390625f + 1e-5f);
    int c = lane * 8;
    float4 g0 = *(const float4*)(gw + c), g1 = *(const float4*)(gw + c + 4);
    float4 b0 = *(const float4*)(bw + c), b1 = *(const float4*)(bw + c + 4);
    float4 o0, o1;
    o0.x = (a.x - mean) * rstd * g0.x + b0.x;
    o0.y = (a.y - mean) * rstd * g0.y + b0.y;
    o0.z = (a.z - mean) * rstd * g0.z + b0.z;
    o0.w = (a.w - mean) * rstd * g0.w + b0.w;
    o1.x = (b.x - mean) * rstd * g1.x + b1.x;
    o1.y = (b.y - mean) * rstd * g1.y + b1.y;
    o1.z = (b.z - mean) * rstd * g1.z + b1.z;
    o1.w = (b.w - mean) * rstd * g1.w + b1.w;
    *(float4*)(Y + row * 256 + c)     = o0;
    *(float4*)(Y + row * 256 + c + 4) = o1;
}

// ---------------- cross-attention + fc + LN + output MLP ----------------
__global__ __launch_bounds__(256) void ca_kernel(
    const float* __restrict__ QH, const float* __restrict__ KH, const float* __restrict__ VH,
    const unsigned char* __restrict__ mask,
    const float* __restrict__ fcw, const float* __restrict__ fcb,
    const float* __restrict__ lng, const float* __restrict__ lnb,
    const float* __restrict__ src, const float* __restrict__ srct,
    const float* __restrict__ w1, const float* __restrict__ b1,
    const float* __restrict__ w2, const float* __restrict__ b2,
    float* __restrict__ out_vec, float* __restrict__ out_attn)
{
    const int b = blockIdx.x;
    const int tid = threadIdx.x;
    __shared__ float s_q[256], s_p[256], s_o[256], s_y[256], s_h[128], s_red[16];

    s_q[tid] = QH[(long)b * 256 + tid];
    __syncthreads();

    const int h = tid >> 7, k = tid & 127;
    const int lane = tid & 31, warp = tid >> 5;

    const float* krow = KH + ((long)b * 128 + k) * 256 + h * 128;
    float s = 0.f;
#pragma unroll 8
    for (int d = 0; d < 128; d += 4) {
        float4 kv = *(const float4*)(krow + d);
        s += s_q[h * 128 + d + 0] * kv.x + s_q[h * 128 + d + 1] * kv.y
           + s_q[h * 128 + d + 2] * kv.z + s_q[h * 128 + d + 3] * kv.w;
    }
    s *= 0.0883883476483184f;
    if (mask[(long)b * 128 + k]) s = -1e10f;

    float mx = s;
#pragma unroll
    for (int o = 16; o > 0; o >>= 1) mx = fmaxf(mx, __shfl_xor_sync(0xffffffffu, mx, o));
    if (lane == 0) s_red[warp] = mx;
    __syncthreads();
    mx = fmaxf(fmaxf(s_red[h * 4 + 0], s_red[h * 4 + 1]),
               fmaxf(s_red[h * 4 + 2], s_red[h * 4 + 3]));
    float e = expf(s - mx);
    float sum = e;
#pragma unroll
    for (int o = 16; o > 0; o >>= 1) sum += __shfl_xor_sync(0xffffffffu, sum, o);
    if (lane == 0) s_red[8 + warp] = sum;
    __syncthreads();
    sum = s_red[8 + h * 4 + 0] + s_red[8 + h * 4 + 1] + s_red[8 + h * 4 + 2] + s_red[8 + h * 4 + 3];
    float p = e / sum;
    s_p[tid] = p;
    out_attn[((long)h * BATCH + b) * 128 + k] = p;
    __syncthreads();

    const int d = tid & 127;
    float o = 0.f;
#pragma unroll 8
    for (int kk = 0; kk < 128; kk++)
        o += s_p[h * 128 + kk] * VH[((long)b * 128 + kk) * 256 + h * 128 + d];
    s_o[tid] = o;
    __syncthreads();

    float y = fcb[tid];
    for (int i = 0; i < 256; i++) y += s_o[i] * fcw[i * 256 + tid];
    y += (tid < 128) ? src[(long)b * 128 + tid] : srct[(long)b * 128 + tid - 128];

    float t = y;
#pragma unroll
    for (int ofs = 16; ofs > 0; ofs >>= 1) t += __shfl_xor_sync(0xffffffffu, t, ofs);
    if (lane == 0) s_red[warp] = t;
    __syncthreads();
    float mean = (s_red[0] + s_red[1] + s_red[2] + s_red[3] +
                  s_red[4] + s_red[5] + s_red[6] + s_red[7]) * 0.00390625f;
    float dv = y - mean;
    t = dv * dv;
#pragma unroll
    for (int ofs = 16; ofs > 0; ofs >>= 1) t += __shfl_xor_sync(0xffffffffu, t, ofs);
    if (lane == 0) s_red[8 + warp] = t;
    __syncthreads();
    float var = (s_red[8] + s_red[9] + s_red[10] + s_red[11] +
                 s_red[12] + s_red[13] + s_red[14] + s_red[15]) * 0.00390625f;
    float rstd = rsqrtf(var + 1e-5f);
    s_y[tid] = dv * rstd * lng[tid] + lnb[tid];
    __syncthreads();

    if (tid < 128) {
        float hh = b1[tid];
        for (int i = 0; i < 256; i++) hh += s_y[i] * w1[i * 128 + tid];
        for (int i = 0; i < 128; i++) hh += src[(long)b * 128 + i] * w1[(256 + i) * 128 + tid];
        s_h[tid] = fmaxf(hh, 0.f);
    }
    __syncthreads();
    if (tid < 128) {
        float oo = b2[tid];
        for (int i = 0; i < 128; i++) oo += s_h[i] * w2[i * 128 + tid];
        out_vec[(long)b * 128 + tid] = oo;
    }
}

// ---------------- host ----------------
static void* sym_addr(const void* s) {
    void* p = nullptr;
    cudaGetSymbolAddress(&p, s);
    return p;
}

extern "C" void kernel_launch(void* const* d_in, const int* in_sizes, int n_in,
                              void* d_out, int out_size)
{
    const float* src   = (const float*)d_in[0];
    const float* srct  = (const float*)d_in[1];
    const float* seq   = (const float*)d_in[2];
    const float* seqt  = (const float*)d_in[3];
    const void*  maskraw = d_in[4];

    const float *sa_wq, *sa_wk, *sa_wv, *sa_fcw, *sa_fcb, *sa_lng, *sa_lnb;
    const float *ms_w1, *ms_b1, *ms_w2, *ms_b2;
    const float *ca_wq, *ca_wk, *ca_wv, *ca_fcw, *ca_fcb, *ca_lng, *ca_lnb;
    const float *mg_w1, *mg_b1, *mg_w2, *mg_b2;

    bool dict_order = (in_sizes[10] == 98304);
    if (dict_order) {
        sa_wq  = (const float*)d_in[5];
        sa_wk  = (const float*)d_in[6];
        sa_wv  = (const float*)d_in[7];
        sa_fcw = (const float*)d_in[8];
        sa_fcb = (const float*)d_in[9];
        ms_w1  = (const float*)d_in[10];
        ms_b1  = (const float*)d_in[11];
        ms_w2  = (const float*)d_in[12];
        ms_b2  = (const float*)d_in[13];
        ca_wq  = (const float*)d_in[14];
        ca_wk  = (const float*)d_in[15];
        ca_wv  = (const float*)d_in[16];
        ca_fcw = (const float*)d_in[17];
        ca_fcb = (const float*)d_in[18];
        mg_w1  = (const float*)d_in[19];
        mg_b1  = (const float*)d_in[20];
        mg_w2  = (const float*)d_in[21];
        mg_b2  = (const float*)d_in[22];
        sa_lng = (const float*)d_in[23];
        sa_lnb = (const float*)d_in[24];
        ca_lng = (const float*)d_in[25];
        ca_lnb = (const float*)d_in[26];
    } else {
        sa_wq  = (const float*)d_in[5];
        sa_wk  = (const float*)d_in[6];
        sa_wv  = (const float*)d_in[7];
        sa_fcw = (const float*)d_in[8];
        sa_fcb = (const float*)d_in[9];
        sa_lng = (const float*)d_in[10];
        sa_lnb = (const float*)d_in[11];
        ms_w1  = (const float*)d_in[12];
        ms_b1  = (const float*)d_in[13];
        ms_w2  = (const float*)d_in[14];
        ms_b2  = (const float*)d_in[15];
        ca_wq  = (const float*)d_in[16];
        ca_wk  = (const float*)d_in[17];
        ca_wv  = (const float*)d_in[18];
        ca_fcw = (const float*)d_in[19];
        ca_fcb = (const float*)d_in[20];
        ca_lng = (const float*)d_in[21];
        ca_lnb = (const float*)d_in[22];
        mg_w1  = (const float*)d_in[23];
        mg_b1  = (const float*)d_in[24];
        mg_w2  = (const float*)d_in[25];
        mg_b2  = (const float*)d_in[26];
    }
    float* out = (float*)d_out;

    float* KV = (float*)sym_addr(g_KV);
    float* Qb = (float*)sym_addr(g_Q);
    float* Kb = (float*)sym_addr(g_K);
    float* Vb = (float*)sym_addr(g_V);
    float* AO = (float*)sym_addr(g_AO);
    float* FC = (float*)sym_addr(g_FC);
    float* SA = (float*)sym_addr(g_SA);
    float* H1 = (float*)sym_addr(g_H1);
    float* KC = (float*)sym_addr(g_KC);
    float* KH = (float*)sym_addr(g_KH);
    float* VH = (float*)sym_addr(g_VH);
    float* QH = (float*)sym_addr(g_QH);
    unsigned char* MK = (unsigned char*)sym_addr(g_mask8);

    const int SMEM_ATTN = SM_ATTN_U32 * 4;     // 206848 bytes
    cudaFuncSetAttribute(sa_attn_kernel, cudaFuncAttributeMaxDynamicSharedMemorySize, SMEM_ATTN);
    const int SMEM_GEMM = SM_GEMM_U32 * 4;     // 40960 bytes (2 CTAs/SM)
    cudaFuncSetAttribute(gemm_tc_kernel, cudaFuncAttributeMaxDynamicSharedMemorySize, SMEM_GEMM);

    detect_mask_kernel<<<1, 32>>>(maskraw);
    norm_mask_kernel<<<NROWS / 256, 256>>>(maskraw);

    concat_kv_kernel<<<ELEMS / 4 / 256, 256>>>(seq, seqt);

    dim3 g2(2, NROWS / 128);
    gemm_tc_kernel<<<g2, 256, SMEM_GEMM>>>(KV, 256, 256, KV, 256, sa_wq, 256, 256, nullptr, nullptr, 0, Qb);
    gemm_tc_kernel<<<g2, 256, SMEM_GEMM>>>(KV, 256, 256, KV, 256, sa_wk, 256, 256, nullptr, nullptr, 0, Kb);
    gemm_tc_kernel<<<g2, 256, SMEM_GEMM>>>(KV, 256, 256, KV, 256, sa_wv, 256, 256, nullptr, nullptr, 0, Vb);

    dim3 ga(2, BATCH);
    sa_attn_kernel<<<ga, 512, SMEM_ATTN>>>(Qb, Kb, Vb, MK, AO);

    gemm_tc_kernel<<<g2, 256, SMEM_GEMM>>>(AO, 256, 256, AO, 256, sa_fcw, 256, 256, sa_fcb, KV, 0, FC);
    ln_kernel<<<NROWS / 8, 256>>>(FC, sa_lng, sa_lnb, SA);

    gemm_tc_kernel<<<g2, 256, SMEM_GEMM>>>(SA, 256, 256, seq, 128, ms_w1, 384, 256, ms_b1, nullptr, 1, H1);
    gemm_tc_kernel<<<g2, 256, SMEM_GEMM>>>(H1, 256, 256, H1, 256, ms_w2, 256, 256, ms_b2, nullptr, 0, KC);

    gemm_tc_kernel<<<g2, 256, SMEM_GEMM>>>(KC, 256, 256, KC, 256, ca_wk, 256, 256, nullptr, nullptr, 0, KH);
    gemm_tc_kernel<<<g2, 256, SMEM_GEMM>>>(KC, 256, 256, KC, 256, ca_wv, 256, 256, nullptr, nullptr, 0, VH);

    dim3 gq(2, BATCH / 128);
    gemm_tc_kernel<<<gq, 256, SMEM_GEMM>>>(src, 128, 128, srct, 128, ca_wq, 256, 256, nullptr, nullptr, 0, QH);

    ca_kernel<<<BATCH, 256>>>(QH, KH, VH, MK,
                              ca_fcw, ca_fcb, ca_lng, ca_lnb,
                              src, srct, mg_w1, mg_b1, mg_w2, mg_b2,
                              out, out + (long)BATCH * 128);
}

// round 16
// speedup vs baseline: 1.2200x; 1.0448x over previous
#include <cuda_runtime.h>
#include <cuda_bf16.h>
#include <math.h>

#define BATCH  1024
#define SEQN   128
#define DMODEL 256
#define NROWS  (BATCH*SEQN)            // 131072
#define ELEMS  (BATCH*SEQN*DMODEL)     // 33554432
#define SST    132

// bf16 GEMM smem layout, u32 units. Row stride = 20 u32 (32 bf16 + pad) = 80 B.
#define RSTR 20
#define UA_H 0
#define UA_L (128*RSTR)
#define UB_H (2*128*RSTR)
#define UB_L (3*128*RSTR)
#define SM_GEMM_U32 (4*128*RSTR)     // 10240 u32 = 40960 B

// sa_attn smem layout (u32 units). Row stride 68 u32. (sPt region removed)
#define QSTR 68
#define OQH 0
#define OQL (128*QSTR)
#define OKH (2*128*QSTR)
#define OKL (3*128*QSTR)
#define SM_ATTN_U32 (4*128*QSTR)     // 34816 u32 = 139264 B

// ---------------- scratch ----------------
__device__ float g_KV[ELEMS];
__device__ float g_Q [ELEMS];
__device__ float g_K [ELEMS];
__device__ float g_V [ELEMS];
__device__ float g_AO[ELEMS];
__device__ float g_FC[ELEMS];
__device__ float g_SA[ELEMS];
__device__ float g_H1[ELEMS];
__device__ float g_KC[ELEMS];
__device__ float g_KH[ELEMS];
__device__ float g_VH[ELEMS];
__device__ float g_QH[BATCH*DMODEL];
__device__ unsigned char g_mask8[NROWS];
__device__ int g_mask_mode;

// ---------------- bf16 helpers ----------------
__device__ __forceinline__ unsigned pack_bf16x2(float lo, float hi) {
    unsigned r;
    asm("cvt.rn.bf16x2.f32 %0, %1, %2;" : "=r"(r) : "f"(hi), "f"(lo));
    return r;
}
__device__ __forceinline__ float lo_bf16f(unsigned u) { return __uint_as_float(u << 16); }
__device__ __forceinline__ float hi_bf16f(unsigned u) { return __uint_as_float(u & 0xFFFF0000u); }
__device__ __forceinline__ void split_pair(float f0, float f1, unsigned& h, unsigned& l) {
    h = pack_bf16x2(f0, f1);
    l = pack_bf16x2(f0 - lo_bf16f(h), f1 - hi_bf16f(h));
}
__device__ __forceinline__ void mma_bf16(float* d, const unsigned* a, const unsigned* b) {
    asm volatile(
        "mma.sync.aligned.m16n8k16.row.col.f32.bf16.bf16.f32 "
        "{%0,%1,%2,%3}, {%4,%5,%6,%7}, {%8,%9}, {%0,%1,%2,%3};\n"
        : "+f"(d[0]), "+f"(d[1]), "+f"(d[2]), "+f"(d[3])
        : "r"(a[0]), "r"(a[1]), "r"(a[2]), "r"(a[3]),
          "r"(b[0]), "r"(b[1]));
}

// ---------------- mask dtype detection + normalization ----------------
__global__ void detect_mask_kernel(const void* mask) {
    if (threadIdx.x == 0 && blockIdx.x == 0) {
        const unsigned* p = (const unsigned*)mask;
        int mode = 1;
        for (int i = 0; i < 1024; i++) {
            unsigned v = p[i];
            if (v == 0x3F800000u) { mode = 2; break; }
            if (v > 1u) { mode = 0; break; }
        }
        g_mask_mode = mode;
    }
}

__global__ __launch_bounds__(256) void norm_mask_kernel(const void* mask) {
    int i = blockIdx.x * 256 + threadIdx.x;
    if (i >= NROWS) return;
    int mode = g_mask_mode;
    unsigned char m;
    if (mode == 0)      m = (((const unsigned char*)mask)[i] != 0);
    else if (mode == 1) m = (((const int*)mask)[i] != 0);
    else                m = (((const float*)mask)[i] != 0.f);
    g_mask8[i] = m;
}

// ---------------- concat([seq, seq_t], -1) -> KV ----------------
__global__ __launch_bounds__(256) void concat_kv_kernel(
    const float* __restrict__ seq, const float* __restrict__ seqt)
{
    long i4 = (long)blockIdx.x * 256 + threadIdx.x;
    if (i4 >= (long)ELEMS / 4) return;
    long row = i4 >> 6;
    int  c4  = (int)(i4 & 63);
    float4 v;
    if (c4 < 32) v = ((const float4*)(seq  + row * 128))[c4];
    else         v = ((const float4*)(seqt + row * 128))[c4 - 32];
    ((float4*)(g_KV + row * 256))[c4] = v;
}

// ---------------- 3xBF16 tensor-core GEMM (R8/R10-proven, UNTOUCHED) ----------------
__global__ __launch_bounds__(256, 2) void gemm_tc_kernel(
    const float* __restrict__ A1, int K1, int lda1,
    const float* __restrict__ A2, int lda2,
    const float* __restrict__ W, int Ktot, int Ncols,
    const float* __restrict__ bias,
    const float* __restrict__ res,
    int relu,
    float* __restrict__ C)
{
    extern __shared__ unsigned su[];
    unsigned* sAh = su + UA_H;
    unsigned* sAl = su + UA_L;
    unsigned* sBh = su + UB_H;
    unsigned* sBl = su + UB_L;

    const int tid  = threadIdx.x;
    const int warp = tid >> 5, lane = tid & 31;
    const int wm = warp & 3, wn = warp >> 2;
    const int group = lane >> 2, tig = lane & 3;
    const long m0 = (long)blockIdx.y * 128;
    const int  n0 = blockIdx.x * 128;
    const int wmb = wm * 32;
    const int wnb = wn * 64;

    float acc[2][8][4];
#pragma unroll
    for (int mi = 0; mi < 2; mi++)
#pragma unroll
        for (int ni = 0; ni < 8; ni++)
#pragma unroll
            for (int q = 0; q < 4; q++) acc[mi][ni][q] = 0.f;

    const int nk = Ktot / 32;

    for (int ck = 0; ck < nk; ck++) {
        const int k0 = ck * 32;
        if (ck > 0) __syncthreads();

#pragma unroll
        for (int i = 0; i < 4; i++) {
            int f4 = tid + i * 256;
            int row = f4 >> 3, c = (f4 & 7) * 4;
            const float* ap = (k0 < K1) ? (A1 + (m0 + row) * (long)lda1 + k0 + c)
                                        : (A2 + (m0 + row) * (long)lda2 + (k0 - K1) + c);
            float4 v = *(const float4*)ap;
            unsigned h0, l0, h1, l1;
            split_pair(v.x, v.y, h0, l0);
            split_pair(v.z, v.w, h1, l1);
            int ui = row * RSTR + (c >> 1);
            *(uint2*)&sAh[ui] = make_uint2(h0, h1);
            *(uint2*)&sAl[ui] = make_uint2(l0, l1);
        }
#pragma unroll
        for (int i = 0; i < 4; i++) {
            int task = tid + i * 256;
            int n  = task & 127;
            int kq = task >> 7;
            const float* wp = W + (long)(k0 + kq * 4) * Ncols + n0 + n;
            float f0 = wp[0];
            float f1 = wp[Ncols];
            float f2 = wp[2 * Ncols];
            float f3 = wp[3 * Ncols];
            unsigned h0, l0, h1, l1;
            split_pair(f0, f1, h0, l0);
            split_pair(f2, f3, h1, l1);
            int ui = n * RSTR + kq * 2;
            *(uint2*)&sBh[ui] = make_uint2(h0, h1);
            *(uint2*)&sBl[ui] = make_uint2(l0, l1);
        }
        __syncthreads();

#pragma unroll
        for (int ks = 0; ks < 2; ks++) {
            const int kb8 = ks * 8;
            unsigned ah[2][4], al[2][4];
#pragma unroll
            for (int mi = 0; mi < 2; mi++) {
                int r = wmb + mi * 16 + group;
                int i0 = r * RSTR + kb8 + tig;
                int i1 = (r + 8) * RSTR + kb8 + tig;
                ah[mi][0] = sAh[i0];
                ah[mi][1] = sAh[i1];
                ah[mi][2] = sAh[i0 + 4];
                ah[mi][3] = sAh[i1 + 4];
                al[mi][0] = sAl[i0];
                al[mi][1] = sAl[i1];
                al[mi][2] = sAl[i0 + 4];
                al[mi][3] = sAl[i1 + 4];
            }
#pragma unroll
            for (int nt = 0; nt < 8; nt++) {
                int nrow = wnb + nt * 8 + group;
                int bi = nrow * RSTR + kb8 + tig;
                unsigned bh[2], bl[2];
                bh[0] = sBh[bi];
                bh[1] = sBh[bi + 4];
                bl[0] = sBl[bi];
                bl[1] = sBl[bi + 4];
#pragma unroll
                for (int mi = 0; mi < 2; mi++) {
                    mma_bf16(acc[mi][nt], ah[mi], bh);
                    mma_bf16(acc[mi][nt], al[mi], bh);
                    mma_bf16(acc[mi][nt], ah[mi], bl);
                }
            }
        }
    }

#pragma unroll
    for (int mi = 0; mi < 2; mi++) {
        long gm = m0 + wmb + mi * 16 + group;
#pragma unroll
        for (int ni = 0; ni < 8; ni++) {
            int gc = n0 + wnb + ni * 8 + 2 * tig;
            float v0 = acc[mi][ni][0], v1 = acc[mi][ni][1];
            float v2 = acc[mi][ni][2], v3 = acc[mi][ni][3];
            if (bias) {
                float b0 = bias[gc], b1 = bias[gc + 1];
                v0 += b0; v1 += b1; v2 += b0; v3 += b1;
            }
            if (res) {
                float2 r0 = *(const float2*)(res + gm * Ncols + gc);
                float2 r1 = *(const float2*)(res + (gm + 8) * Ncols + gc);
                v0 += r0.x; v1 += r0.y; v2 += r1.x; v3 += r1.y;
            }
            if (relu) {
                v0 = fmaxf(v0, 0.f); v1 = fmaxf(v1, 0.f);
                v2 = fmaxf(v2, 0.f); v3 = fmaxf(v3, 0.f);
            }
            *(float2*)(C + gm * Ncols + gc)       = make_float2(v0, v1);
            *(float2*)(C + (gm + 8) * Ncols + gc) = make_float2(v2, v3);
        }
    }
}

// ---------------- fused multi-output GEMM: same body, W/C selected once per block ----------------
// Single A source, lda=256, K=256, N=256, no bias/res/relu.
// grid.x = 2 * n_outputs; sel = blockIdx.x >> 1; n0 = (blockIdx.x & 1) * 128.
__global__ __launch_bounds__(256, 2) void gemm_tc_multi_kernel(
    const float* __restrict__ A,
    const float* __restrict__ W0, const float* __restrict__ W1, const float* __restrict__ W2,
    float* __restrict__ C0, float* __restrict__ C1, float* __restrict__ C2)
{
    extern __shared__ unsigned su[];
    unsigned* sAh = su + UA_H;
    unsigned* sAl = su + UA_L;
    unsigned* sBh = su + UB_H;
    unsigned* sBl = su + UB_L;

    const int sel = blockIdx.x >> 1;
    const float* __restrict__ W = (sel == 0) ? W0 : (sel == 1) ? W1 : W2;
    float* __restrict__ C = (sel == 0) ? C0 : (sel == 1) ? C1 : C2;

    const int tid  = threadIdx.x;
    const int warp = tid >> 5, lane = tid & 31;
    const int wm = warp & 3, wn = warp >> 2;
    const int group = lane >> 2, tig = lane & 3;
    const long m0 = (long)blockIdx.y * 128;
    const int  n0 = (blockIdx.x & 1) * 128;
    const int wmb = wm * 32;
    const int wnb = wn * 64;

    float acc[2][8][4];
#pragma unroll
    for (int mi = 0; mi < 2; mi++)
#pragma unroll
        for (int ni = 0; ni < 8; ni++)
#pragma unroll
            for (int q = 0; q < 4; q++) acc[mi][ni][q] = 0.f;

    for (int ck = 0; ck < 8; ck++) {
        const int k0 = ck * 32;
        if (ck > 0) __syncthreads();

#pragma unroll
        for (int i = 0; i < 4; i++) {
            int f4 = tid + i * 256;
            int row = f4 >> 3, c = (f4 & 7) * 4;
            float4 v = *(const float4*)(A + (m0 + row) * 256L + k0 + c);
            unsigned h0, l0, h1, l1;
            split_pair(v.x, v.y, h0, l0);
            split_pair(v.z, v.w, h1, l1);
            int ui = row * RSTR + (c >> 1);
            *(uint2*)&sAh[ui] = make_uint2(h0, h1);
            *(uint2*)&sAl[ui] = make_uint2(l0, l1);
        }
#pragma unroll
        for (int i = 0; i < 4; i++) {
            int task = tid + i * 256;
            int n  = task & 127;
            int kq = task >> 7;
            const float* wp = W + (long)(k0 + kq * 4) * 256 + n0 + n;
            float f0 = wp[0];
            float f1 = wp[256];
            float f2 = wp[512];
            float f3 = wp[768];
            unsigned h0, l0, h1, l1;
            split_pair(f0, f1, h0, l0);
            split_pair(f2, f3, h1, l1);
            int ui = n * RSTR + kq * 2;
            *(uint2*)&sBh[ui] = make_uint2(h0, h1);
            *(uint2*)&sBl[ui] = make_uint2(l0, l1);
        }
        __syncthreads();

#pragma unroll
        for (int ks = 0; ks < 2; ks++) {
            const int kb8 = ks * 8;
            unsigned ah[2][4], al[2][4];
#pragma unroll
            for (int mi = 0; mi < 2; mi++) {
                int r = wmb + mi * 16 + group;
                int i0 = r * RSTR + kb8 + tig;
                int i1 = (r + 8) * RSTR + kb8 + tig;
                ah[mi][0] = sAh[i0];
                ah[mi][1] = sAh[i1];
                ah[mi][2] = sAh[i0 + 4];
                ah[mi][3] = sAh[i1 + 4];
                al[mi][0] = sAl[i0];
                al[mi][1] = sAl[i1];
                al[mi][2] = sAl[i0 + 4];
                al[mi][3] = sAl[i1 + 4];
            }
#pragma unroll
            for (int nt = 0; nt < 8; nt++) {
                int nrow = wnb + nt * 8 + group;
                int bi = nrow * RSTR + kb8 + tig;
                unsigned bh[2], bl[2];
                bh[0] = sBh[bi];
                bh[1] = sBh[bi + 4];
                bl[0] = sBl[bi];
                bl[1] = sBl[bi + 4];
#pragma unroll
                for (int mi = 0; mi < 2; mi++) {
                    mma_bf16(acc[mi][nt], ah[mi], bh);
                    mma_bf16(acc[mi][nt], al[mi], bh);
                    mma_bf16(acc[mi][nt], ah[mi], bl);
                }
            }
        }
    }

#pragma unroll
    for (int mi = 0; mi < 2; mi++) {
        long gm = m0 + wmb + mi * 16 + group;
#pragma unroll
        for (int ni = 0; ni < 8; ni++) {
            int gc = n0 + wnb + ni * 8 + 2 * tig;
            *(float2*)(C + gm * 256 + gc)       = make_float2(acc[mi][ni][0], acc[mi][ni][1]);
            *(float2*)(C + (gm + 8) * 256 + gc) = make_float2(acc[mi][ni][2], acc[mi][ni][3]);
        }
    }
}

// ---------------- self-attention: bf16 TC, 512 thr, register-resident softmax ----------------
__global__ __launch_bounds__(512) void sa_attn_kernel(
    const float* __restrict__ Q, const float* __restrict__ K, const float* __restrict__ V,
    const unsigned char* __restrict__ mask, float* __restrict__ O)
{
    extern __shared__ unsigned su[];
    __shared__ unsigned char smask[128];
    __shared__ float smax[128][4];
    __shared__ float ssum[128][4];

    const int h = blockIdx.x, b = blockIdx.y;
    const int tid = threadIdx.x;
    const int warp = tid >> 5, lane = tid & 31;
    const int group = lane >> 2, tig = lane & 3;
    const float* Qp = Q + ((long)b * SEQN) * DMODEL + h * 128;
    const float* Kp = K + ((long)b * SEQN) * DMODEL + h * 128;
    const float* Vp = V + ((long)b * SEQN) * DMODEL + h * 128;
    const float invs = 0.0883883476483184f;

    const int wm = warp & 3;
    const int wn = warp >> 2;           // 0..3
    const int wmb = wm * 32, wnb = wn * 32;

    if (tid < 128) smask[tid] = mask[(long)b * SEQN + tid];
    // ---- load + pack Q(scaled), K -> hi/lo [row][kp] ----
    for (int idx = tid; idx < 128 * 32; idx += 512) {
        int r = idx >> 5;
        int c = (idx & 31) << 2;
        int ui = r * QSTR + (c >> 1);
        float4 qv = *(const float4*)(Qp + (long)r * DMODEL + c);
        qv.x *= invs; qv.y *= invs; qv.z *= invs; qv.w *= invs;
        unsigned h0, l0, h1, l1;
        split_pair(qv.x, qv.y, h0, l0);
        split_pair(qv.z, qv.w, h1, l1);
        *(uint2*)&su[OQH + ui] = make_uint2(h0, h1);
        *(uint2*)&su[OQL + ui] = make_uint2(l0, l1);
        float4 kv = *(const float4*)(Kp + (long)r * DMODEL + c);
        split_pair(kv.x, kv.y, h0, l0);
        split_pair(kv.z, kv.w, h1, l1);
        *(uint2*)&su[OKH + ui] = make_uint2(h0, h1);
        *(uint2*)&su[OKL + ui] = make_uint2(l0, l1);
    }
    __syncthreads();

    // ---- S = Qs · K^T into registers ----
    float acc[2][4][4];
#pragma unroll
    for (int mi = 0; mi < 2; mi++)
#pragma unroll
        for (int ni = 0; ni < 4; ni++)
#pragma unroll
            for (int q = 0; q < 4; q++) acc[mi][ni][q] = 0.f;

#pragma unroll
    for (int ks = 0; ks < 8; ks++) {
        const int kb8 = ks * 8;
        unsigned ah[2][4], al[2][4];
#pragma unroll
        for (int mi = 0; mi < 2; mi++) {
            int r = wmb + mi * 16 + group;
            int i0 = r * QSTR + kb8 + tig;
            int i1 = (r + 8) * QSTR + kb8 + tig;
            ah[mi][0] = su[OQH + i0];
            ah[mi][1] = su[OQH + i1];
            ah[mi][2] = su[OQH + i0 + 4];
            ah[mi][3] = su[OQH + i1 + 4];
            al[mi][0] = su[OQL + i0];
            al[mi][1] = su[OQL + i1];
            al[mi][2] = su[OQL + i0 + 4];
            al[mi][3] = su[OQL + i1 + 4];
        }
#pragma unroll
        for (int nt = 0; nt < 4; nt++) {
            int nrow = wnb + nt * 8 + group;
            int bi = nrow * QSTR + kb8 + tig;
            unsigned bh[2], bl[2];
            bh[0] = su[OKH + bi];
            bh[1] = su[OKH + bi + 4];
            bl[0] = su[OKL + bi];
            bl[1] = su[OKL + bi + 4];
#pragma unroll
            for (int mi = 0; mi < 2; mi++) {
                mma_bf16(acc[mi][nt], ah[mi], bh);
                mma_bf16(acc[mi][nt], al[mi], bh);
                mma_bf16(acc[mi][nt], ah[mi], bl);
            }
        }
    }
    __syncthreads();   // all warps done reading Q/K regions

    // ---- pack V^T [d][kp] into K region (runs before/with softmax; covered by later syncs) ----
    for (int idx = tid; idx < 64 * 32; idx += 512) {
        int kplow = idx & 15;
        int rest  = idx >> 4;
        int c4 = rest & 31;
        int kp = (rest >> 5) * 16 + kplow;
        int c = c4 * 4;
        float4 v0 = *(const float4*)(Vp + (long)(2 * kp) * DMODEL + c);
        float4 v1 = *(const float4*)(Vp + (long)(2 * kp + 1) * DMODEL + c);
        unsigned hh, ll;
        split_pair(v0.x, v1.x, hh, ll);
        su[OKH + (c + 0) * QSTR + kp] = hh; su[OKL + (c + 0) * QSTR + kp] = ll;
        split_pair(v0.y, v1.y, hh, ll);
        su[OKH + (c + 1) * QSTR + kp] = hh; su[OKL + (c + 1) * QSTR + kp] = ll;
        split_pair(v0.z, v1.z, hh, ll);
        su[OKH + (c + 2) * QSTR + kp] = hh; su[OKL + (c + 2) * QSTR + kp] = ll;
        split_pair(v0.w, v1.w, hh, ll);
        su[OKH + (c + 3) * QSTR + kp] = hh; su[OKL + (c + 3) * QSTR + kp] = ll;
    }

    // ---- mask + local row max (registers) ----
#pragma unroll
    for (int mi = 0; mi < 2; mi++) {
        float m0 = -1e30f, m1 = -1e30f;
#pragma unroll
        for (int nt = 0; nt < 4; nt++) {
            int c0 = wnb + nt * 8 + 2 * tig;
            if (smask[c0])     { acc[mi][nt][0] = -1e10f; acc[mi][nt][2] = -1e10f; }
            if (smask[c0 + 1]) { acc[mi][nt][1] = -1e10f; acc[mi][nt][3] = -1e10f; }
            m0 = fmaxf(m0, fmaxf(acc[mi][nt][0], acc[mi][nt][1]));
            m1 = fmaxf(m1, fmaxf(acc[mi][nt][2], acc[mi][nt][3]));
        }
        m0 = fmaxf(m0, __shfl_xor_sync(0xffffffffu, m0, 1));
        m0 = fmaxf(m0, __shfl_xor_sync(0xffffffffu, m0, 2));
        m1 = fmaxf(m1, __shfl_xor_sync(0xffffffffu, m1, 1));
        m1 = fmaxf(m1, __shfl_xor_sync(0xffffffffu, m1, 2));
        if (tig == 0) {
            smax[wmb + mi * 16 + group][wn]     = m0;
            smax[wmb + mi * 16 + group + 8][wn] = m1;
        }
    }
    __syncthreads();

    // ---- global max, exp, local sums ----
    float rm0[2], rm1[2];
#pragma unroll
    for (int mi = 0; mi < 2; mi++) {
        int r0 = wmb + mi * 16 + group, r1 = r0 + 8;
        float4 v0 = *(const float4*)smax[r0];
        float4 v1 = *(const float4*)smax[r1];
        rm0[mi] = fmaxf(fmaxf(v0.x, v0.y), fmaxf(v0.z, v0.w));
        rm1[mi] = fmaxf(fmaxf(v1.x, v1.y), fmaxf(v1.z, v1.w));
        float s0 = 0.f, s1 = 0.f;
#pragma unroll
        for (int nt = 0; nt < 4; nt++) {
            acc[mi][nt][0] = expf(acc[mi][nt][0] - rm0[mi]); s0 += acc[mi][nt][0];
            acc[mi][nt][1] = expf(acc[mi][nt][1] - rm0[mi]); s0 += acc[mi][nt][1];
            acc[mi][nt][2] = expf(acc[mi][nt][2] - rm1[mi]); s1 += acc[mi][nt][2];
            acc[mi][nt][3] = expf(acc[mi][nt][3] - rm1[mi]); s1 += acc[mi][nt][3];
        }
        s0 += __shfl_xor_sync(0xffffffffu, s0, 1);
        s0 += __shfl_xor_sync(0xffffffffu, s0, 2);
        s1 += __shfl_xor_sync(0xffffffffu, s1, 1);
        s1 += __shfl_xor_sync(0xffffffffu, s1, 2);
        if (tig == 0) {
            ssum[r0][wn] = s0;
            ssum[r1][wn] = s1;
        }
    }
    __syncthreads();

    // ---- normalize + pack P [q][kp] directly from registers into Q region ----
#pragma unroll
    for (int mi = 0; mi < 2; mi++) {
        int r0 = wmb + mi * 16 + group, r1 = r0 + 8;
        float4 u0 = *(const float4*)ssum[r0];
        float4 u1 = *(const float4*)ssum[r1];
        float inv0 = 1.f / (u0.x + u0.y + u0.z + u0.w);
        float inv1 = 1.f / (u1.x + u1.y + u1.z + u1.w);
#pragma unroll
        for (int nt = 0; nt < 4; nt++) {
            int kp = wn * 16 + nt * 4 + tig;
            unsigned hh, ll;
            split_pair(acc[mi][nt][0] * inv0, acc[mi][nt][1] * inv0, hh, ll);
            su[OQH + r0 * QSTR + kp] = hh;
            su[OQL + r0 * QSTR + kp] = ll;
            split_pair(acc[mi][nt][2] * inv1, acc[mi][nt][3] * inv1, hh, ll);
            su[OQH + r1 * QSTR + kp] = hh;
            su[OQL + r1 * QSTR + kp] = ll;
        }
    }
    __syncthreads();

    // ---- O = P · V ----
    {
        float oacc[2][4][4];
#pragma unroll
        for (int mi = 0; mi < 2; mi++)
#pragma unroll
            for (int ni = 0; ni < 4; ni++)
#pragma unroll
                for (int q = 0; q < 4; q++) oacc[mi][ni][q] = 0.f;

#pragma unroll
        for (int ks = 0; ks < 8; ks++) {
            const int kb8 = ks * 8;
            unsigned ah[2][4], al[2][4];
#pragma unroll
            for (int mi = 0; mi < 2; mi++) {
                int r = wmb + mi * 16 + group;
                int i0 = r * QSTR + kb8 + tig;
                int i1 = (r + 8) * QSTR + kb8 + tig;
                ah[mi][0] = su[OQH + i0];
                ah[mi][1] = su[OQH + i1];
                ah[mi][2] = su[OQH + i0 + 4];
                ah[mi][3] = su[OQH + i1 + 4];
                al[mi][0] = su[OQL + i0];
                al[mi][1] = su[OQL + i1];
                al[mi][2] = su[OQL + i0 + 4];
                al[mi][3] = su[OQL + i1 + 4];
            }
#pragma unroll
            for (int nt = 0; nt < 4; nt++) {
                int nrow = wnb + nt * 8 + group;
                int bi = nrow * QSTR + kb8 + tig;
                unsigned bh[2], bl[2];
                bh[0] = su[OKH + bi];
                bh[1] = su[OKH + bi + 4];
                bl[0] = su[OKL + bi];
                bl[1] = su[OKL + bi + 4];
#pragma unroll
                for (int mi = 0; mi < 2; mi++) {
                    mma_bf16(oacc[mi][nt], ah[mi], bh);
                    mma_bf16(oacc[mi][nt], al[mi], bh);
                    mma_bf16(oacc[mi][nt], ah[mi], bl);
                }
            }
        }

        float* Op = O + ((long)b * SEQN) * DMODEL + h * 128;
#pragma unroll
        for (int mi = 0; mi < 2; mi++) {
            int gm = wmb + mi * 16 + group;
#pragma unroll
            for (int nt = 0; nt < 4; nt++) {
                int gc = wnb + nt * 8 + 2 * tig;
                *(float2*)(Op + (long)gm * DMODEL + gc)       = make_float2(oacc[mi][nt][0], oacc[mi][nt][1]);
                *(float2*)(Op + (long)(gm + 8) * DMODEL + gc) = make_float2(oacc[mi][nt][2], oacc[mi][nt][3]);
            }
        }
    }
}

// ---------------- LayerNorm over 256, warp per row ----------------
__global__ __launch_bounds__(256) void ln_kernel(
    const float* __restrict__ X, const float* __restrict__ gw,
    const float* __restrict__ bw, float* __restrict__ Y)
{
    long row = (long)blockIdx.x * 8 + (threadIdx.x >> 5);
    int lane = threadIdx.x & 31;
    const float* xp = X + row * 256 + lane * 8;
    float4 a = *(const float4*)xp;
    float4 b = *(const float4*)(xp + 4);
    float s = a.x + a.y + a.z + a.w + b.x + b.y + b.z + b.w;
#pragma unroll
    for (int o = 16; o > 0; o >>= 1) s += __shfl_xor_sync(0xffffffffu, s, o);
    float mean = s * 0.00390625f;
    float q = 0.f;
    q += (a.x - mean) * (a.x - mean); q += (a.y - mean) * (a.y - mean);
    q += (a.z - mean) * (a.z - mean); q += (a.w - mean) * (a.w - mean);
    q += (b.x - mean) * (b.x - mean); q += (b.y - mean) * (b.y - mean);
    q += (b.z - mean) * (b.z - mean); q += (b.w - mean) * (b.w - mean);
#pragma unroll
    for (int o = 16; o > 0; o >>= 1) q += __shfl_xor_sync(0xffffffffu, q, o);
    float rstd = rsqrtf(q * 0.00390625f + 1e-5f);
    int c = lane * 8;
    float4 g0 = *(const float4*)(gw + c), g1 = *(const float4*)(gw + c + 4);
    float4 b0 = *(const float4*)(bw + c), b1 = *(const float4*)(bw + c + 4);
    float4 o0, o1;
    o0.x = (a.x - mean) * rstd * g0.x + b0.x;
    o0.y = (a.y - mean) * rstd * g0.y + b0.y;
    o0.z = (a.z - mean) * rstd * g0.z + b0.z;
    o0.w = (a.w - mean) * rstd * g0.w + b0.w;
    o1.x = (b.x - mean) * rstd * g1.x + b1.x;
    o1.y = (b.y - mean) * rstd * g1.y + b1.y;
    o1.z = (b.z - mean) * rstd * g1.z + b1.z;
    o1.w = (b.w - mean) * rstd * g1.w + b1.w;
    *(float4*)(Y + row * 256 + c)     = o0;
    *(float4*)(Y + row * 256 + c + 4) = o1;
}

// ---------------- cross-attention + fc + LN + output MLP ----------------
__global__ __launch_bounds__(256) void ca_kernel(
    const float* __restrict__ QH, const float* __restrict__ KH, const float* __restrict__ VH,
    const unsigned char* __restrict__ mask,
    const float* __restrict__ fcw, const float* __restrict__ fcb,
    const float* __restrict__ lng, const float* __restrict__ lnb,
    const float* __restrict__ src, const float* __restrict__ srct,
    const float* __restrict__ w1, const float* __restrict__ b1,
    const float* __restrict__ w2, const float* __restrict__ b2,
    float* __restrict__ out_vec, float* __restrict__ out_attn)
{
    const int b = blockIdx.x;
    const int tid = threadIdx.x;
    __shared__ float s_q[256], s_p[256], s_o[256], s_y[256], s_h[128], s_red[16];

    s_q[tid] = QH[(long)b * 256 + tid];
    __syncthreads();

    const int h = tid >> 7, k = tid & 127;
    const int lane = tid & 31, warp = tid >> 5;

    const float* krow = KH + ((long)b * 128 + k) * 256 + h * 128;
    float s = 0.f;
#pragma unroll 8
    for (int d = 0; d < 128; d += 4) {
        float4 kv = *(const float4*)(krow + d);
        s += s_q[h * 128 + d + 0] * kv.x + s_q[h * 128 + d + 1] * kv.y
           + s_q[h * 128 + d + 2] * kv.z + s_q[h * 128 + d + 3] * kv.w;
    }
    s *= 0.0883883476483184f;
    if (mask[(long)b * 128 + k]) s = -1e10f;

    float mx = s;
#pragma unroll
    for (int o = 16; o > 0; o >>= 1) mx = fmaxf(mx, __shfl_xor_sync(0xffffffffu, mx, o));
    if (lane == 0) s_red[warp] = mx;
    __syncthreads();
    mx = fmaxf(fmaxf(s_red[h * 4 + 0], s_red[h * 4 + 1]),
               fmaxf(s_red[h * 4 + 2], s_red[h * 4 + 3]));
    float e = expf(s - mx);
    float sum = e;
#pragma unroll
    for (int o = 16; o > 0; o >>= 1) sum += __shfl_xor_sync(0xffffffffu, sum, o);
    if (lane == 0) s_red[8 + warp] = sum;
    __syncthreads();
    sum = s_red[8 + h * 4 + 0] + s_red[8 + h * 4 + 1] + s_red[8 + h * 4 + 2] + s_red[8 + h * 4 + 3];
    float p = e / sum;
    s_p[tid] = p;
    out_attn[((long)h * BATCH + b) * 128 + k] = p;
    __syncthreads();

    const int d = tid & 127;
    float o = 0.f;
#pragma unroll 8
    for (int kk = 0; kk < 128; kk++)
        o += s_p[h * 128 + kk] * VH[((long)b * 128 + kk) * 256 + h * 128 + d];
    s_o[tid] = o;
    __syncthreads();

    float y = fcb[tid];
    for (int i = 0; i < 256; i++) y += s_o[i] * fcw[i * 256 + tid];
    y += (tid < 128) ? src[(long)b * 128 + tid] : srct[(long)b * 128 + tid - 128];

    float t = y;
#pragma unroll
    for (int ofs = 16; ofs > 0; ofs >>= 1) t += __shfl_xor_sync(0xffffffffu, t, ofs);
    if (lane == 0) s_red[warp] = t;
    __syncthreads();
    float mean = (s_red[0] + s_red[1] + s_red[2] + s_red[3] +
                  s_red[4] + s_red[5] + s_red[6] + s_red[7]) * 0.00390625f;
    float dv = y - mean;
    t = dv * dv;
#pragma unroll
    for (int ofs = 16; ofs > 0; ofs >>= 1) t += __shfl_xor_sync(0xffffffffu, t, ofs);
    if (lane == 0) s_red[8 + warp] = t;
    __syncthreads();
    float var = (s_red[8] + s_red[9] + s_red[10] + s_red[11] +
                 s_red[12] + s_red[13] + s_red[14] + s_red[15]) * 0.00390625f;
    float rstd = rsqrtf(var + 1e-5f);
    s_y[tid] = dv * rstd * lng[tid] + lnb[tid];
    __syncthreads();

    if (tid < 128) {
        float hh = b1[tid];
        for (int i = 0; i < 256; i++) hh += s_y[i] * w1[i * 128 + tid];
        for (int i = 0; i < 128; i++) hh += src[(long)b * 128 + i] * w1[(256 + i) * 128 + tid];
        s_h[tid] = fmaxf(hh, 0.f);
    }
    __syncthreads();
    if (tid < 128) {
        float oo = b2[tid];
        for (int i = 0; i < 128; i++) oo += s_h[i] * w2[i * 128 + tid];
        out_vec[(long)b * 128 + tid] = oo;
    }
}

// ---------------- host ----------------
static void* sym_addr(const void* s) {
    void* p = nullptr;
    cudaGetSymbolAddress(&p, s);
    return p;
}

extern "C" void kernel_launch(void* const* d_in, const int* in_sizes, int n_in,
                              void* d_out, int out_size)
{
    const float* src   = (const float*)d_in[0];
    const float* srct  = (const float*)d_in[1];
    const float* seq   = (const float*)d_in[2];
    const float* seqt  = (const float*)d_in[3];
    const void*  maskraw = d_in[4];

    const float *sa_wq, *sa_wk, *sa_wv, *sa_fcw, *sa_fcb, *sa_lng, *sa_lnb;
    const float *ms_w1, *ms_b1, *ms_w2, *ms_b2;
    const float *ca_wq, *ca_wk, *ca_wv, *ca_fcw, *ca_fcb, *ca_lng, *ca_lnb;
    const float *mg_w1, *mg_b1, *mg_w2, *mg_b2;

    bool dict_order = (in_sizes[10] == 98304);
    if (dict_order) {
        sa_wq  = (const float*)d_in[5];
        sa_wk  = (const float*)d_in[6];
        sa_wv  = (const float*)d_in[7];
        sa_fcw = (const float*)d_in[8];
        sa_fcb = (const float*)d_in[9];
        ms_w1  = (const float*)d_in[10];
        ms_b1  = (const float*)d_in[11];
        ms_w2  = (const float*)d_in[12];
        ms_b2  = (const float*)d_in[13];
        ca_wq  = (const float*)d_in[14];
        ca_wk  = (const float*)d_in[15];
        ca_wv  = (const float*)d_in[16];
        ca_fcw = (const float*)d_in[17];
        ca_fcb = (const float*)d_in[18];
        mg_w1  = (const float*)d_in[19];
        mg_b1  = (const float*)d_in[20];
        mg_w2  = (const float*)d_in[21];
        mg_b2  = (const float*)d_in[22];
        sa_lng = (const float*)d_in[23];
        sa_lnb = (const float*)d_in[24];
        ca_lng = (const float*)d_in[25];
        ca_lnb = (const float*)d_in[26];
    } else {
        sa_wq  = (const float*)d_in[5];
        sa_wk  = (const float*)d_in[6];
        sa_wv  = (const float*)d_in[7];
        sa_fcw = (const float*)d_in[8];
        sa_fcb = (const float*)d_in[9];
        sa_lng = (const float*)d_in[10];
        sa_lnb = (const float*)d_in[11];
        ms_w1  = (const float*)d_in[12];
        ms_b1  = (const float*)d_in[13];
        ms_w2  = (const float*)d_in[14];
        ms_b2  = (const float*)d_in[15];
        ca_wq  = (const float*)d_in[16];
        ca_wk  = (const float*)d_in[17];
        ca_wv  = (const float*)d_in[18];
        ca_fcw = (const float*)d_in[19];
        ca_fcb = (const float*)d_in[20];
        ca_lng = (const float*)d_in[21];
        ca_lnb = (const float*)d_in[22];
        mg_w1  = (const float*)d_in[23];
        mg_b1  = (const float*)d_in[24];
        mg_w2  = (const float*)d_in[25];
        mg_b2  = (const float*)d_in[26];
    }
    float* out = (float*)d_out;

    float* KV = (float*)sym_addr(g_KV);
    float* Qb = (float*)sym_addr(g_Q);
    float* Kb = (float*)sym_addr(g_K);
    float* Vb = (float*)sym_addr(g_V);
    float* AO = (float*)sym_addr(g_AO);
    float* FC = (float*)sym_addr(g_FC);
    float* SA = (float*)sym_addr(g_SA);
    float* H1 = (float*)sym_addr(g_H1);
    float* KC = (float*)sym_addr(g_KC);
    float* KH = (float*)sym_addr(g_KH);
    float* VH = (float*)sym_addr(g_VH);
    float* QH = (float*)sym_addr(g_QH);
    unsigned char* MK = (unsigned char*)sym_addr(g_mask8);

    const int SMEM_ATTN = SM_ATTN_U32 * 4;     // 139264 bytes
    cudaFuncSetAttribute(sa_attn_kernel, cudaFuncAttributeMaxDynamicSharedMemorySize, SMEM_ATTN);
    const int SMEM_GEMM = SM_GEMM_U32 * 4;     // 40960 bytes (2 CTAs/SM)
    cudaFuncSetAttribute(gemm_tc_kernel, cudaFuncAttributeMaxDynamicSharedMemorySize, SMEM_GEMM);
    cudaFuncSetAttribute(gemm_tc_multi_kernel, cudaFuncAttributeMaxDynamicSharedMemorySize, SMEM_GEMM);

    detect_mask_kernel<<<1, 32>>>(maskraw);
    norm_mask_kernel<<<NROWS / 256, 256>>>(maskraw);

    concat_kv_kernel<<<ELEMS / 4 / 256, 256>>>(seq, seqt);

    // fused Q/K/V projections (A = KV read once)
    gemm_tc_multi_kernel<<<dim3(6, NROWS / 128), 256, SMEM_GEMM>>>(
        KV, sa_wq, sa_wk, sa_wv, Qb, Kb, Vb);

    dim3 ga(2, BATCH);
    sa_attn_kernel<<<ga, 512, SMEM_ATTN>>>(Qb, Kb, Vb, MK, AO);

    dim3 g2(2, NROWS / 128);
    gemm_tc_kernel<<<g2, 256, SMEM_GEMM>>>(AO, 256, 256, AO, 256, sa_fcw, 256, 256, sa_fcb, KV, 0, FC);
    ln_kernel<<<NROWS / 8, 256>>>(FC, sa_lng, sa_lnb, SA);

    gemm_tc_kernel<<<g2, 256, SMEM_GEMM>>>(SA, 256, 256, seq, 128, ms_w1, 384, 256, ms_b1, nullptr, 1, H1);
    gemm_tc_kernel<<<g2, 256, SMEM_GEMM>>>(H1, 256, 256, H1, 256, ms_w2, 256, 256, ms_b2, nullptr, 0, KC);

    // fused ca K/V projections (A = KC read once)
    gemm_tc_multi_kernel<<<dim3(4, NROWS / 128), 256, SMEM_GEMM>>>(
        KC, ca_wk, ca_wv, ca_wv, KH, VH, VH);

    dim3 gq(2, BATCH / 128);
    gemm_tc_kernel<<<gq, 256, SMEM_GEMM>>>(src, 128, 128, srct, 128, ca_wq, 256, 256, nullptr, nullptr, 0, QH);

    ca_kernel<<<BATCH, 256>>>(QH, KH, VH, MK,
                              ca_fcw, ca_fcb, ca_lng, ca_lnb,
                              src, srct, mg_w1, mg_b1, mg_w2, mg_b2,
                              out, out + (long)BATCH * 128);
}